// round 10
// baseline (speedup 1.0000x reference)
#include <cuda_runtime.h>
#include <math.h>

#define NB 8
#define M1N 2000
#define M2N 400
#define ATN 2400
#define NN (NB*ATN)
#define HD 64
#define NGN 50
#define ATTR_P 56
#define LN 4
#define CN 4
#define E1N 60000
#define E2N 20000
#define E3N 20000
#define ETN 100000

typedef unsigned long long u64;

__device__ float g_h[NN*HD];
__device__ float g_x[3][NN*HD];
__device__ float g_agg[3][NN*HD];
__device__ float g_W[LN*ETN*HD];
__device__ float g_attr[ETN*ATTR_P];
__device__ float g_ccut[ETN];
__device__ int   g_csrsrc[ETN];
__device__ int   g_csrw[ETN];
__device__ int   g_cnt[3*ATN];    // zero-init; re-zeroed by k_cleanup each run
__device__ int   g_cur[3*ATN];
__device__ int   g_rs[3*(ATN+1)];
__device__ int   g_cc[3*CN];
__device__ int   g_ccur[3*CN];
__device__ int   g_cbase[3*(CN+1)];

__device__ __forceinline__ float sspf(float x){
    return fmaxf(x, 0.0f) + log1pf(__expf(-fabsf(x))) - 0.6931471805599453f;
}

__device__ __forceinline__ void fma2(u64& d, u64 a, u64 b){
    asm("fma.rn.f32x2 %0, %1, %2, %0;" : "+l"(d) : "l"(a), "l"(b));
}

__device__ __forceinline__ void resolve_edge(int idx, int& g, int& e, int& eofs){
    if(idx < E1N){ g = 0; e = idx; eofs = 0; }
    else if(idx < E1N+E2N){ g = 1; e = idx-E1N; eofs = E1N; }
    else { g = 2; e = idx-E1N-E2N; eofs = E1N+E2N; }
}

// ---------------- preprocessing ----------------
__global__ void k_count(const int* __restrict__ e1, const int* __restrict__ e2,
                        const int* __restrict__ e3,
                        const int* __restrict__ c1, const int* __restrict__ c2,
                        const int* __restrict__ c3){
    int idx = blockIdx.x*blockDim.x + threadIdx.x;
    if(idx >= ETN) return;
    int g, e, eofs; resolve_edge(idx, g, e, eofs);
    const int* cp  = (g==0) ? c1 : ((g==1) ? c2 : c3);
    const int* eip = (g==0) ? e1 : ((g==1) ? e2 : e3);
    atomicAdd(&g_cc[g*CN + cp[e]], 1);
    atomicAdd(&g_cnt[g*ATN + eip[2*e + 1]], 1);
}

__global__ void k_cbase_rs(){
    int g = blockIdx.x;
    int lane = threadIdx.x;
    if(lane == 0){
        int s = 0;
        g_cbase[g*(CN+1)] = 0;
        for(int c = 0; c < CN; c++){ s += g_cc[g*CN + c]; g_cbase[g*(CN+1)+c+1] = s; }
    }
    const int per = ATN / 32;
    int base = lane * per;
    int sum = 0;
    for(int i = 0; i < per; i++) sum += g_cnt[g*ATN + base + i];
    int incl = sum;
    #pragma unroll
    for(int o = 1; o < 32; o <<= 1){
        int v = __shfl_up_sync(0xFFFFFFFFu, incl, o);
        if(lane >= o) incl += v;
    }
    int run = incl - sum;
    for(int i = 0; i < per; i++){
        g_rs[g*(ATN+1) + base + i] = run;
        run += g_cnt[g*ATN + base + i];
    }
    if(lane == 31) g_rs[g*(ATN+1) + ATN] = run;
}

__global__ void k_fill(const int* __restrict__ e1, const int* __restrict__ e2,
                       const int* __restrict__ e3,
                       const float* __restrict__ w1, const float* __restrict__ w2,
                       const float* __restrict__ w3,
                       const int* __restrict__ c1, const int* __restrict__ c2,
                       const int* __restrict__ c3){
    int idx = blockIdx.x*blockDim.x + threadIdx.x;
    if(idx >= ETN) return;
    int g, e, eofs; resolve_edge(idx, g, e, eofs);
    const int* cp  = (g==0) ? c1 : ((g==1) ? c2 : c3);
    const int* eip = (g==0) ? e1 : ((g==1) ? e2 : e3);
    const float* wp = (g==0) ? w1 : ((g==1) ? w2 : w3);
    int col = cp[e];
    float d = wp[e];
    int p = g_cbase[g*(CN+1)+col] + atomicAdd(&g_ccur[g*CN+col], 1);
    g_ccut[eofs + p] = 0.5f * (cosf(d * 3.14159265358979323846f / 10.0f) + 1.0f);
    const float step = 10.0f / 49.0f;
    const float coeff = -0.5f / (step*step);
    float4* ap = (float4*)&g_attr[(size_t)(eofs + p)*ATTR_P];
    #pragma unroll
    for(int q = 0; q < ATTR_P/4; q++){
        float4 v;
        float t0 = d - step*(float)(4*q+0);
        float t1 = d - step*(float)(4*q+1);
        float t2 = d - step*(float)(4*q+2);
        float t3 = d - step*(float)(4*q+3);
        v.x = __expf(coeff*t0*t0); v.y = __expf(coeff*t1*t1);
        v.z = __expf(coeff*t2*t2); v.w = __expf(coeff*t3*t3);
        ap[q] = v;
    }
    int src = eip[2*e], dst = eip[2*e + 1];
    int pc = g_rs[g*(ATN+1) + dst] + atomicAdd(&g_cur[g*ATN + dst], 1);
    g_csrsrc[eofs + pc] = src;
    g_csrw[eofs + pc] = p;
}

__global__ void k_embed(const int* __restrict__ sites, const int* __restrict__ sitesp,
                        const float* __restrict__ embw, const float* __restrict__ embpw){
    int idx = blockIdx.x*blockDim.x + threadIdx.x;
    if(idx >= NN*HD) return;
    int n = idx >> 6, f = idx & 63;
    int b = n / ATN, i = n - b*ATN;
    float v;
    if(i < M1N) v = embw[sites[b*M1N + i]*HD + f];
    else        v = embpw[sitesp[b*M2N + (i - M1N)]*HD + f];
    g_h[idx] = v;
}

__global__ void k_cleanup(){
    int i = blockIdx.x*blockDim.x + threadIdx.x;
    if(i < 3*ATN){ g_cnt[i] = 0; g_cur[i] = 0; }
    if(i < 3*CN){ g_cc[i] = 0; g_ccur[i] = 0; }
}

// ---------------- edge-filter MLP: 64x64 tile, 128 thr, 4 rows x 8 cols/thread ----
// tc = t&7 (8 col-groups of 8), tr = t>>3 (16 row-groups of 4)
__global__ void k_wmlp(const float* __restrict__ mw1, const float* __restrict__ mb1,
                       const float* __restrict__ mw2, const float* __restrict__ mb2,
                       int g, int eofs){
    const int c = blockIdx.y, l = blockIdx.z;
    const int cb = g_cbase[g*(CN+1)+c];
    const int ce = g_cbase[g*(CN+1)+c+1];
    const int r0 = cb + blockIdx.x*64;
    if(r0 >= ce) return;
    const int t = threadIdx.x;
    const int tc = t & 7, tr = t >> 3;

    __shared__ __align__(16) float sW[64*64];
    __shared__ __align__(16) float sU[64*65];   // attr tile, then H tile

    const int pgc = (l*3 + g)*CN + c;
    const float* w1 = mw1 + pgc*NGN*HD;
    for(int i = t; i < NGN*HD; i += 128) sW[i] = w1[i];
    for(int i = t; i < 64*NGN; i += 128){
        int rr = i / NGN, kk = i - rr*NGN;
        int row = r0 + rr;
        sU[rr*65 + kk] = (row < ce) ? g_attr[(size_t)(eofs + row)*ATTR_P + kk] : 0.0f;
    }
    __syncthreads();

    float acc[4][8];
    #pragma unroll
    for(int ri = 0; ri < 4; ri++)
        #pragma unroll
        for(int j = 0; j < 8; j++) acc[ri][j] = 0.0f;
    for(int k = 0; k < NGN; k++){
        float4 wa = *(const float4*)&sW[k*64 + tc*8];
        float4 wb = *(const float4*)&sW[k*64 + tc*8 + 4];
        #pragma unroll
        for(int ri = 0; ri < 4; ri++){
            float a = sU[(tr*4 + ri)*65 + k];
            acc[ri][0] += a*wa.x; acc[ri][1] += a*wa.y;
            acc[ri][2] += a*wa.z; acc[ri][3] += a*wa.w;
            acc[ri][4] += a*wb.x; acc[ri][5] += a*wb.y;
            acc[ri][6] += a*wb.z; acc[ri][7] += a*wb.w;
        }
    }
    __syncthreads();      // all reads of sU (attr) and sW (w1) done

    float b1v[8];
    #pragma unroll
    for(int j = 0; j < 8; j++) b1v[j] = mb1[pgc*HD + tc*8 + j];
    #pragma unroll
    for(int ri = 0; ri < 4; ri++)
        #pragma unroll
        for(int j = 0; j < 8; j++)
            sU[(tr*4 + ri)*65 + tc*8 + j] = sspf(acc[ri][j] + b1v[j]);
    const float* w2 = mw2 + pgc*HD*HD;
    for(int i = t; i < HD*HD; i += 128) sW[i] = w2[i];
    __syncthreads();

    float acc2[4][8];
    #pragma unroll
    for(int ri = 0; ri < 4; ri++)
        #pragma unroll
        for(int j = 0; j < 8; j++) acc2[ri][j] = 0.0f;
    for(int k = 0; k < HD; k++){
        float4 wa = *(const float4*)&sW[k*64 + tc*8];
        float4 wb = *(const float4*)&sW[k*64 + tc*8 + 4];
        #pragma unroll
        for(int ri = 0; ri < 4; ri++){
            float a = sU[(tr*4 + ri)*65 + k];
            acc2[ri][0] += a*wa.x; acc2[ri][1] += a*wa.y;
            acc2[ri][2] += a*wa.z; acc2[ri][3] += a*wa.w;
            acc2[ri][4] += a*wb.x; acc2[ri][5] += a*wb.y;
            acc2[ri][6] += a*wb.z; acc2[ri][7] += a*wb.w;
        }
    }
    float b2v[8];
    #pragma unroll
    for(int j = 0; j < 8; j++) b2v[j] = mb2[pgc*HD + tc*8 + j];
    #pragma unroll
    for(int ri = 0; ri < 4; ri++){
        int row = r0 + tr*4 + ri;
        if(row < ce){
            float cc = g_ccut[eofs + row];
            float4* dp = (float4*)&g_W[(size_t)(l*ETN + eofs + row)*HD + tc*8];
            dp[0] = make_float4((acc2[ri][0]+b2v[0])*cc, (acc2[ri][1]+b2v[1])*cc,
                                (acc2[ri][2]+b2v[2])*cc, (acc2[ri][3]+b2v[3])*cc);
            dp[1] = make_float4((acc2[ri][4]+b2v[4])*cc, (acc2[ri][5]+b2v[5])*cc,
                                (acc2[ri][6]+b2v[6])*cc, (acc2[ri][7]+b2v[7])*cc);
        }
    }
}

// ---------------- lin1: 64-row tile, 4 rows x 8 cols/thread ----------------
__global__ void k_lin1(const float* __restrict__ cw1, int l){
    const int gph = blockIdx.y;
    const int r0 = blockIdx.x * 64;
    const int t = threadIdx.x, tc = t & 7, tr = t >> 3;
    __shared__ __align__(16) float sW[64*64];
    __shared__ float sHt[64*65];
    const float* w = cw1 + (l*3 + gph)*HD*HD;
    for(int i = t; i < HD*HD; i += 128) sW[i] = w[i];
    for(int i = t; i < 64*64; i += 128){
        int rr = i >> 6, kk = i & 63;
        sHt[rr*65 + kk] = g_h[(r0 + rr)*HD + kk];
    }
    __syncthreads();
    float acc[4][8];
    #pragma unroll
    for(int ri = 0; ri < 4; ri++)
        #pragma unroll
        for(int j = 0; j < 8; j++) acc[ri][j] = 0.0f;
    for(int k = 0; k < HD; k++){
        float4 wa = *(const float4*)&sW[k*64 + tc*8];
        float4 wb = *(const float4*)&sW[k*64 + tc*8 + 4];
        #pragma unroll
        for(int ri = 0; ri < 4; ri++){
            float a = sHt[(tr*4 + ri)*65 + k];
            acc[ri][0] += a*wa.x; acc[ri][1] += a*wa.y;
            acc[ri][2] += a*wa.z; acc[ri][3] += a*wa.w;
            acc[ri][4] += a*wb.x; acc[ri][5] += a*wb.y;
            acc[ri][6] += a*wb.z; acc[ri][7] += a*wb.w;
        }
    }
    float* xo = g_x[gph];
    #pragma unroll
    for(int ri = 0; ri < 4; ri++){
        int row = r0 + tr*4 + ri;
        float4* dp = (float4*)&xo[row*HD + tc*8];
        dp[0] = make_float4(acc[ri][0], acc[ri][1], acc[ri][2], acc[ri][3]);
        dp[1] = make_float4(acc[ri][4], acc[ri][5], acc[ri][6], acc[ri][7]);
    }
}

// ---------------- CSR aggregation: 1 warp per dst, u64 lanes ----------------
__global__ void k_agg(int l){
    const int gph = blockIdx.y;
    const int t = threadIdx.x;
    const int f2 = t & 31;
    const int dq = t >> 5;
    const int dst = blockIdx.x*8 + dq;
    const int eofs = (gph == 0) ? 0 : ((gph == 1) ? E1N : (E1N + E2N));
    const int s = g_rs[gph*(ATN+1) + dst];
    const int e = g_rs[gph*(ATN+1) + dst + 1];
    const u64* __restrict__ xq = (const u64*)g_x[gph];
    const u64* __restrict__ Wq = (const u64*)(g_W + (size_t)l*ETN*HD) + (size_t)eofs*32;
    u64 acc[NB];
    #pragma unroll
    for(int b = 0; b < NB; b++) acc[b] = 0ull;
    int src = 0, wp = 0;
    if(s < e){ src = __ldg(&g_csrsrc[eofs + s]); wp = __ldg(&g_csrw[eofs + s]); }
    for(int p = s; p < e; p++){
        int ns = 0, nw = 0;
        if(p + 1 < e){ ns = __ldg(&g_csrsrc[eofs + p + 1]); nw = __ldg(&g_csrw[eofs + p + 1]); }
        u64 w = Wq[(size_t)wp*32 + f2];
        int base = src*32 + f2;
        #pragma unroll
        for(int b = 0; b < NB; b++)
            fma2(acc[b], xq[base + b*ATN*32], w);
        src = ns; wp = nw;
    }
    u64* aq = (u64*)g_agg[gph];
    int ob = dst*32 + f2;
    #pragma unroll
    for(int b = 0; b < NB; b++)
        aq[ob + b*ATN*32] = acc[b];
}

// ---------------- block: 32-row tile, 2 rows x 8 cols/thread, fused 3 graphs ----
__global__ void k_block(const float* __restrict__ cw2, const float* __restrict__ cb2,
                        const float* __restrict__ bw, const float* __restrict__ bb,
                        int l){
    const int r0 = blockIdx.x * 32;
    const int t = threadIdx.x, tc = t & 7, tr = t >> 3;   // rows tr*2+ri, ri<2
    __shared__ __align__(16) float sW[64*64];
    __shared__ float sAg[32*65];
    __shared__ float sT[32*65];
    float hacc[2][8];
    #pragma unroll
    for(int ri = 0; ri < 2; ri++)
        #pragma unroll
        for(int j = 0; j < 8; j++) hacc[ri][j] = 0.0f;

    for(int g = 0; g < 3; g++){
        const float* w = cw2 + (l*3 + g)*HD*HD;
        for(int i = t; i < HD*HD; i += 128) sW[i] = w[i];
        const float* ag = g_agg[g];
        for(int i = t; i < 32*64; i += 128){
            int rr = i >> 6, kk = i & 63;
            sAg[rr*65 + kk] = ag[(r0 + rr)*HD + kk];
        }
        __syncthreads();

        float acc[2][8];
        #pragma unroll
        for(int ri = 0; ri < 2; ri++)
            #pragma unroll
            for(int j = 0; j < 8; j++) acc[ri][j] = 0.0f;
        for(int k = 0; k < HD; k++){
            float4 wa = *(const float4*)&sW[k*64 + tc*8];
            float4 wb = *(const float4*)&sW[k*64 + tc*8 + 4];
            #pragma unroll
            for(int ri = 0; ri < 2; ri++){
                float a = sAg[(tr*2 + ri)*65 + k];
                acc[ri][0] += a*wa.x; acc[ri][1] += a*wa.y;
                acc[ri][2] += a*wa.z; acc[ri][3] += a*wa.w;
                acc[ri][4] += a*wb.x; acc[ri][5] += a*wb.y;
                acc[ri][6] += a*wb.z; acc[ri][7] += a*wb.w;
            }
        }
        float b2v[8];
        #pragma unroll
        for(int j = 0; j < 8; j++) b2v[j] = cb2[(l*3 + g)*HD + tc*8 + j];
        #pragma unroll
        for(int ri = 0; ri < 2; ri++)
            #pragma unroll
            for(int j = 0; j < 8; j++)
                sT[(tr*2 + ri)*65 + tc*8 + j] = sspf(acc[ri][j] + b2v[j]);
        __syncthreads();

        const float* w2 = bw + (l*3 + g)*HD*HD;
        for(int i = t; i < HD*HD; i += 128) sW[i] = w2[i];
        __syncthreads();

        for(int k = 0; k < HD; k++){
            float4 wa = *(const float4*)&sW[k*64 + tc*8];
            float4 wb = *(const float4*)&sW[k*64 + tc*8 + 4];
            #pragma unroll
            for(int ri = 0; ri < 2; ri++){
                float a = sT[(tr*2 + ri)*65 + k];
                hacc[ri][0] += a*wa.x; hacc[ri][1] += a*wa.y;
                hacc[ri][2] += a*wa.z; hacc[ri][3] += a*wa.w;
                hacc[ri][4] += a*wb.x; hacc[ri][5] += a*wb.y;
                hacc[ri][6] += a*wb.z; hacc[ri][7] += a*wb.w;
            }
        }
        float bbv[8];
        #pragma unroll
        for(int j = 0; j < 8; j++) bbv[j] = bb[(l*3 + g)*HD + tc*8 + j];
        #pragma unroll
        for(int ri = 0; ri < 2; ri++)
            #pragma unroll
            for(int j = 0; j < 8; j++) hacc[ri][j] += bbv[j];
        __syncthreads();
    }

    #pragma unroll
    for(int ri = 0; ri < 2; ri++){
        int row = r0 + tr*2 + ri;
        float4* hp = (float4*)&g_h[row*HD + tc*8];
        float4 h0 = hp[0], h1 = hp[1];
        h0.x += hacc[ri][0]; h0.y += hacc[ri][1];
        h0.z += hacc[ri][2]; h0.w += hacc[ri][3];
        h1.x += hacc[ri][4]; h1.y += hacc[ri][5];
        h1.z += hacc[ri][6]; h1.w += hacc[ri][7];
        hp[0] = h0; hp[1] = h1;
    }
}

__global__ void k_readout(const float* __restrict__ ow1, const float* __restrict__ ob1,
                          const float* __restrict__ ow2, const float* __restrict__ ob2,
                          float* __restrict__ out){
    __shared__ float sS[NB*HD];
    __shared__ float sV[NB*32];
    int t = threadIdx.x;
    int b = t >> 6, f = t & 63;
    float s = 0.0f;
    const float* hp = g_h + (size_t)(b*ATN + M1N)*HD + f;
    #pragma unroll 4
    for(int i = 0; i < M2N; i++) s += hp[(size_t)i*HD];
    sS[b*HD + f] = s;
    __syncthreads();
    if(t < NB*32){
        int b2 = t >> 5, j = t & 31;
        float v = 0.0f;
        #pragma unroll 8
        for(int f2 = 0; f2 < HD; f2++) v += sS[b2*HD + f2] * ow1[f2*32 + j];
        sV[b2*32 + j] = v + (float)M2N * ob1[j];
    }
    __syncthreads();
    if(t < NB){
        float o = 0.0f;
        #pragma unroll
        for(int j = 0; j < 32; j++) o += sV[t*32 + j] * ow2[j];
        out[t] = o + (float)M2N * ob2[0];
    }
}

extern "C" void kernel_launch(void* const* d_in, const int* in_sizes, int n_in,
                              void* d_out, int out_size){
    (void)in_sizes; (void)n_in; (void)out_size;
    const int*   sites  = (const int*)d_in[0];
    const int*   sitesp = (const int*)d_in[1];
    const int*   ei1 = (const int*)d_in[2];
    const float* ew1 = (const float*)d_in[3];
    const int*   c1  = (const int*)d_in[4];
    const int*   ei2 = (const int*)d_in[5];
    const float* ew2 = (const float*)d_in[6];
    const int*   c2  = (const int*)d_in[7];
    const int*   ei3 = (const int*)d_in[8];
    const float* ew3 = (const float*)d_in[9];
    const int*   c3  = (const int*)d_in[10];
    const float* embw  = (const float*)d_in[11];
    const float* embpw = (const float*)d_in[12];
    const float* mw1 = (const float*)d_in[13];
    const float* mb1 = (const float*)d_in[14];
    const float* mw2 = (const float*)d_in[15];
    const float* mb2 = (const float*)d_in[16];
    const float* cw1 = (const float*)d_in[17];
    const float* cw2 = (const float*)d_in[18];
    const float* cb2 = (const float*)d_in[19];
    const float* bw  = (const float*)d_in[20];
    const float* bb  = (const float*)d_in[21];
    const float* ow1 = (const float*)d_in[22];
    const float* ob1 = (const float*)d_in[23];
    const float* ow2 = (const float*)d_in[24];
    const float* ob2 = (const float*)d_in[25];
    float* out = (float*)d_out;

    k_count<<<(ETN + 255)/256, 256>>>(ei1, ei2, ei3, c1, c2, c3);               // 1
    k_cbase_rs<<<3, 32>>>();                                                    // 2
    k_fill<<<(ETN + 255)/256, 256>>>(ei1, ei2, ei3, ew1, ew2, ew3, c1, c2, c3); // 3

    dim3 gw0((E1N + 63)/64, CN, LN);
    dim3 gw1((E2N + 63)/64, CN, LN);
    dim3 gw2((E3N + 63)/64, CN, LN);
    k_wmlp<<<gw0, 128>>>(mw1, mb1, mw2, mb2, 0, 0);                             // 4 <- profiled
    k_wmlp<<<gw1, 128>>>(mw1, mb1, mw2, mb2, 1, E1N);
    k_wmlp<<<gw2, 128>>>(mw1, mb1, mw2, mb2, 2, E1N + E2N);
    k_embed<<<(NN*HD + 255)/256, 256>>>(sites, sitesp, embw, embpw);

    for(int l = 0; l < LN; l++){
        k_lin1<<<dim3(NN/64, 3), 128>>>(cw1, l);
        k_agg<<<dim3(ATN/8, 3), 256>>>(l);
        k_block<<<NN/32, 128>>>(cw2, cb2, bw, bb, l);
    }
    k_readout<<<1, 512>>>(ow1, ob1, ow2, ob2, out);
    k_cleanup<<<(3*ATN + 255)/256, 256>>>();
}

// round 11
// speedup vs baseline: 1.3213x; 1.3213x over previous
#include <cuda_runtime.h>
#include <math.h>

#define NB 8
#define M1N 2000
#define M2N 400
#define ATN 2400
#define NN (NB*ATN)
#define HD 64
#define NGN 50
#define ATTR_P 56
#define NBUK 50
#define LN 4
#define CN 4
#define E1N 60000
#define E2N 20000
#define E3N 20000
#define ETN 100000

typedef unsigned long long u64;

__device__ float g_h[NN*HD];
__device__ float g_x[3][NN*HD];
__device__ float g_agg[3][NN*HD];
__device__ float g_W[LN*ETN*HD];
__device__ float g_attr[ETN*ATTR_P];
__device__ float g_ccut[ETN];
__device__ int   g_kq[ETN];
__device__ int   g_csrsrc[ETN];
__device__ int   g_csrw[ETN];
__device__ int   g_cnt[3*ATN];        // zero-init; re-zeroed by k_cleanup
__device__ int   g_cur[3*ATN];
__device__ int   g_rs[3*(ATN+1)];
__device__ int   g_cc2[3*CN*NBUK];    // (g,color,bucket) counters
__device__ int   g_ccur2[3*CN*NBUK];
__device__ int   g_cb2[3*CN*NBUK];    // exclusive prefix per g

__device__ __forceinline__ float sspf(float x){
    return fmaxf(x, 0.0f) + log1pf(__expf(-fabsf(x))) - 0.6931471805599453f;
}

__device__ __forceinline__ void fma2(u64& d, u64 a, u64 b){
    asm("fma.rn.f32x2 %0, %1, %2, %0;" : "+l"(d) : "l"(a), "l"(b));
}

__device__ __forceinline__ int bucket_of(float d){
    int b = (int)(d * 4.9f);          // d/step, step = 10/49
    return min(NBUK-1, max(0, b));
}

__device__ __forceinline__ void resolve_edge(int idx, int& g, int& e, int& eofs){
    if(idx < E1N){ g = 0; e = idx; eofs = 0; }
    else if(idx < E1N+E2N){ g = 1; e = idx-E1N; eofs = E1N; }
    else { g = 2; e = idx-E1N-E2N; eofs = E1N+E2N; }
}

// ---------------- preprocessing ----------------
__global__ void k_count(const int* __restrict__ e1, const int* __restrict__ e2,
                        const int* __restrict__ e3,
                        const float* __restrict__ w1, const float* __restrict__ w2,
                        const float* __restrict__ w3,
                        const int* __restrict__ c1, const int* __restrict__ c2,
                        const int* __restrict__ c3){
    int idx = blockIdx.x*blockDim.x + threadIdx.x;
    if(idx >= ETN) return;
    int g, e, eofs; resolve_edge(idx, g, e, eofs);
    const int* cp  = (g==0) ? c1 : ((g==1) ? c2 : c3);
    const int* eip = (g==0) ? e1 : ((g==1) ? e2 : e3);
    const float* wp = (g==0) ? w1 : ((g==1) ? w2 : w3);
    int b = bucket_of(wp[e]);
    atomicAdd(&g_cc2[(g*CN + cp[e])*NBUK + b], 1);
    atomicAdd(&g_cnt[g*ATN + eip[2*e + 1]], 1);
}

__global__ void k_cbase_rs(){
    int g = blockIdx.x;
    int lane = threadIdx.x;
    // CSR row scan (2400 rows)
    {
        const int per = ATN / 32;
        int base = lane * per;
        int sum = 0;
        for(int i = 0; i < per; i++) sum += g_cnt[g*ATN + base + i];
        int incl = sum;
        #pragma unroll
        for(int o = 1; o < 32; o <<= 1){
            int v = __shfl_up_sync(0xFFFFFFFFu, incl, o);
            if(lane >= o) incl += v;
        }
        int run = incl - sum;
        for(int i = 0; i < per; i++){
            g_rs[g*(ATN+1) + base + i] = run;
            run += g_cnt[g*ATN + base + i];
        }
        if(lane == 31) g_rs[g*(ATN+1) + ATN] = run;
    }
    // (color,bucket) scan: 200 entries
    {
        const int M = CN*NBUK;           // 200
        const int per = (M + 31) / 32;   // 7
        int base = lane * per;
        int sum = 0;
        for(int i = 0; i < per; i++){
            int id = base + i;
            if(id < M) sum += g_cc2[g*M + id];
        }
        int incl = sum;
        #pragma unroll
        for(int o = 1; o < 32; o <<= 1){
            int v = __shfl_up_sync(0xFFFFFFFFu, incl, o);
            if(lane >= o) incl += v;
        }
        int run = incl - sum;
        for(int i = 0; i < per; i++){
            int id = base + i;
            if(id < M){ g_cb2[g*M + id] = run; run += g_cc2[g*M + id]; }
        }
    }
}

__global__ void k_fill(const int* __restrict__ e1, const int* __restrict__ e2,
                       const int* __restrict__ e3,
                       const float* __restrict__ w1, const float* __restrict__ w2,
                       const float* __restrict__ w3,
                       const int* __restrict__ c1, const int* __restrict__ c2,
                       const int* __restrict__ c3){
    int idx = blockIdx.x*blockDim.x + threadIdx.x;
    if(idx >= ETN) return;
    int g, e, eofs; resolve_edge(idx, g, e, eofs);
    const int* cp  = (g==0) ? c1 : ((g==1) ? c2 : c3);
    const int* eip = (g==0) ? e1 : ((g==1) ? e2 : e3);
    const float* wp = (g==0) ? w1 : ((g==1) ? w2 : w3);
    int col = cp[e];
    float d = wp[e];
    int b = bucket_of(d);
    int slot = (g*CN + col)*NBUK + b;
    int p = g_cb2[slot] + atomicAdd(&g_ccur2[slot], 1);
    g_kq[eofs + p] = b;
    g_ccut[eofs + p] = 0.5f * (cosf(d * 3.14159265358979323846f / 10.0f) + 1.0f);
    const float step = 10.0f / 49.0f;
    const float coeff = -0.5f / (step*step);
    float4* ap = (float4*)&g_attr[(size_t)(eofs + p)*ATTR_P];
    #pragma unroll
    for(int q = 0; q < ATTR_P/4; q++){
        float4 v;
        float t0 = d - step*(float)(4*q+0);
        float t1 = d - step*(float)(4*q+1);
        float t2 = d - step*(float)(4*q+2);
        float t3 = d - step*(float)(4*q+3);
        v.x = __expf(coeff*t0*t0); v.y = __expf(coeff*t1*t1);
        v.z = __expf(coeff*t2*t2); v.w = __expf(coeff*t3*t3);
        ap[q] = v;
    }
    int src = eip[2*e], dst = eip[2*e + 1];
    int pc = g_rs[g*(ATN+1) + dst] + atomicAdd(&g_cur[g*ATN + dst], 1);
    g_csrsrc[eofs + pc] = src;
    g_csrw[eofs + pc] = p;
}

__global__ void k_embed(const int* __restrict__ sites, const int* __restrict__ sitesp,
                        const float* __restrict__ embw, const float* __restrict__ embpw){
    int idx = blockIdx.x*blockDim.x + threadIdx.x;
    if(idx >= NN*HD) return;
    int n = idx >> 6, f = idx & 63;
    int b = n / ATN, i = n - b*ATN;
    float v;
    if(i < M1N) v = embw[sites[b*M1N + i]*HD + f];
    else        v = embpw[sitesp[b*M2N + (i - M1N)]*HD + f];
    g_h[idx] = v;
}

__global__ void k_cleanup(){
    int i = blockIdx.x*blockDim.x + threadIdx.x;
    if(i < 3*ATN){ g_cnt[i] = 0; g_cur[i] = 0; }
    if(i < 3*CN*NBUK){ g_cc2[i] = 0; g_ccur2[i] = 0; }
}

// ---------------- edge-filter MLP (R9 union form + windowed GEMM-1) ----------------
__global__ void k_wmlp(const float* __restrict__ mw1, const float* __restrict__ mb1,
                       const float* __restrict__ mw2, const float* __restrict__ mb2,
                       int g, int eofs, int etot){
    const int c = blockIdx.y, l = blockIdx.z;
    const int cb = g_cb2[(g*CN + c)*NBUK];
    const int ce = (c == CN-1) ? etot : g_cb2[(g*CN + c + 1)*NBUK];
    const int r0 = cb + blockIdx.x*64;
    if(r0 >= ce) return;
    const int t = threadIdx.x;
    const int tc = t & 15, tr = t >> 4;

    __shared__ __align__(16) float sW[64*64];
    __shared__ __align__(16) float sU[64*65];   // attr tile, then H tile

    // tile gaussian window from bucket-sorted rows
    const int b0 = g_kq[eofs + r0];
    const int b1 = g_kq[eofs + min(r0 + 63, ce - 1)];
    const int k0 = max(0, b0 - 6);
    const int kend = min(NGN - 1, b1 + 7);

    const int pgc = (l*3 + g)*CN + c;
    const float* w1 = mw1 + pgc*NGN*HD;
    for(int i = t; i < NGN*HD; i += 128) sW[i] = w1[i];
    for(int i = t; i < 64*NGN; i += 128){
        int rr = i / NGN, kk = i - rr*NGN;
        int row = r0 + rr;
        sU[rr*65 + kk] = (row < ce) ? g_attr[(size_t)(eofs + row)*ATTR_P + kk] : 0.0f;
    }
    __syncthreads();

    float acc[8][4];
    #pragma unroll
    for(int ri = 0; ri < 8; ri++){ acc[ri][0]=0; acc[ri][1]=0; acc[ri][2]=0; acc[ri][3]=0; }
    for(int k = k0; k <= kend; k++){
        float4 w = *(const float4*)&sW[k*64 + tc*4];
        #pragma unroll
        for(int ri = 0; ri < 8; ri++){
            float a = sU[(tr*8 + ri)*65 + k];
            acc[ri][0] += a*w.x; acc[ri][1] += a*w.y;
            acc[ri][2] += a*w.z; acc[ri][3] += a*w.w;
        }
    }
    __syncthreads();      // reads of sU (attr) and sW (w1) done

    float b1v[4];
    #pragma unroll
    for(int j = 0; j < 4; j++) b1v[j] = mb1[pgc*HD + tc*4 + j];
    #pragma unroll
    for(int ri = 0; ri < 8; ri++)
        #pragma unroll
        for(int j = 0; j < 4; j++)
            sU[(tr*8 + ri)*65 + tc*4 + j] = sspf(acc[ri][j] + b1v[j]);
    const float* w2 = mw2 + pgc*HD*HD;
    for(int i = t; i < HD*HD; i += 128) sW[i] = w2[i];
    __syncthreads();

    float acc2[8][4];
    #pragma unroll
    for(int ri = 0; ri < 8; ri++){ acc2[ri][0]=0; acc2[ri][1]=0; acc2[ri][2]=0; acc2[ri][3]=0; }
    for(int k = 0; k < HD; k++){
        float4 w = *(const float4*)&sW[k*64 + tc*4];
        #pragma unroll
        for(int ri = 0; ri < 8; ri++){
            float a = sU[(tr*8 + ri)*65 + k];
            acc2[ri][0] += a*w.x; acc2[ri][1] += a*w.y;
            acc2[ri][2] += a*w.z; acc2[ri][3] += a*w.w;
        }
    }
    float b2v[4];
    #pragma unroll
    for(int j = 0; j < 4; j++) b2v[j] = mb2[pgc*HD + tc*4 + j];
    #pragma unroll
    for(int ri = 0; ri < 8; ri++){
        int row = r0 + tr*8 + ri;
        if(row < ce){
            float cc = g_ccut[eofs + row];
            float4 o;
            o.x = (acc2[ri][0] + b2v[0]) * cc;
            o.y = (acc2[ri][1] + b2v[1]) * cc;
            o.z = (acc2[ri][2] + b2v[2]) * cc;
            o.w = (acc2[ri][3] + b2v[3]) * cc;
            *(float4*)&g_W[(size_t)(l*ETN + eofs + row)*HD + tc*4] = o;
        }
    }
}

// ---------------- lin1 (R9 form) ----------------
__global__ void k_lin1(const float* __restrict__ cw1, int l){
    const int gph = blockIdx.y;
    const int r0 = blockIdx.x * 64;
    const int t = threadIdx.x, tc = t & 15, tr = t >> 4;
    __shared__ __align__(16) float sW[64*64];
    __shared__ float sHt[64*65];
    const float* w = cw1 + (l*3 + gph)*HD*HD;
    for(int i = t; i < HD*HD; i += 128) sW[i] = w[i];
    for(int i = t; i < 64*64; i += 128){
        int rr = i >> 6, kk = i & 63;
        sHt[rr*65 + kk] = g_h[(r0 + rr)*HD + kk];
    }
    __syncthreads();
    float acc[8][4];
    #pragma unroll
    for(int ri = 0; ri < 8; ri++){ acc[ri][0]=0; acc[ri][1]=0; acc[ri][2]=0; acc[ri][3]=0; }
    for(int k = 0; k < HD; k++){
        float4 w4 = *(const float4*)&sW[k*64 + tc*4];
        #pragma unroll
        for(int ri = 0; ri < 8; ri++){
            float a = sHt[(tr*8 + ri)*65 + k];
            acc[ri][0] += a*w4.x; acc[ri][1] += a*w4.y;
            acc[ri][2] += a*w4.z; acc[ri][3] += a*w4.w;
        }
    }
    float* xo = g_x[gph];
    #pragma unroll
    for(int ri = 0; ri < 8; ri++){
        int row = r0 + tr*8 + ri;
        float4 o; o.x = acc[ri][0]; o.y = acc[ri][1]; o.z = acc[ri][2]; o.w = acc[ri][3];
        *(float4*)&xo[row*HD + tc*4] = o;
    }
}

// ---------------- CSR aggregation (R9 form) ----------------
__global__ void k_agg(int l){
    const int gph = blockIdx.y;
    const int t = threadIdx.x;
    const int f2 = t & 31;
    const int dq = t >> 5;
    const int dst = blockIdx.x*8 + dq;
    const int eofs = (gph == 0) ? 0 : ((gph == 1) ? E1N : (E1N + E2N));
    const int s = g_rs[gph*(ATN+1) + dst];
    const int e = g_rs[gph*(ATN+1) + dst + 1];
    const u64* __restrict__ xq = (const u64*)g_x[gph];
    const u64* __restrict__ Wq = (const u64*)(g_W + (size_t)l*ETN*HD) + (size_t)eofs*32;
    u64 acc[NB];
    #pragma unroll
    for(int b = 0; b < NB; b++) acc[b] = 0ull;
    int src = 0, wp = 0;
    if(s < e){ src = __ldg(&g_csrsrc[eofs + s]); wp = __ldg(&g_csrw[eofs + s]); }
    for(int p = s; p < e; p++){
        int ns = 0, nw = 0;
        if(p + 1 < e){ ns = __ldg(&g_csrsrc[eofs + p + 1]); nw = __ldg(&g_csrw[eofs + p + 1]); }
        u64 w = Wq[(size_t)wp*32 + f2];
        int base = src*32 + f2;
        #pragma unroll
        for(int b = 0; b < NB; b++)
            fma2(acc[b], xq[base + b*ATN*32], w);
        src = ns; wp = nw;
    }
    u64* aq = (u64*)g_agg[gph];
    int ob = dst*32 + f2;
    #pragma unroll
    for(int b = 0; b < NB; b++)
        aq[ob + b*ATN*32] = acc[b];
}

// ---------------- block (R9 32-row form) ----------------
__global__ void k_block(const float* __restrict__ cw2, const float* __restrict__ cb2,
                        const float* __restrict__ bw, const float* __restrict__ bb,
                        int l){
    const int r0 = blockIdx.x * 32;
    const int t = threadIdx.x, tc = t & 15, tr = t >> 4;
    __shared__ __align__(16) float sW[64*64];
    __shared__ float sAg[32*65];
    __shared__ float sT[32*65];
    float hacc[4][4];
    #pragma unroll
    for(int ri = 0; ri < 4; ri++){ hacc[ri][0]=0; hacc[ri][1]=0; hacc[ri][2]=0; hacc[ri][3]=0; }

    for(int g = 0; g < 3; g++){
        const float* w = cw2 + (l*3 + g)*HD*HD;
        for(int i = t; i < HD*HD; i += 128) sW[i] = w[i];
        const float* ag = g_agg[g];
        for(int i = t; i < 32*64; i += 128){
            int rr = i >> 6, kk = i & 63;
            sAg[rr*65 + kk] = ag[(r0 + rr)*HD + kk];
        }
        __syncthreads();

        float acc[4][4];
        #pragma unroll
        for(int ri = 0; ri < 4; ri++){ acc[ri][0]=0; acc[ri][1]=0; acc[ri][2]=0; acc[ri][3]=0; }
        for(int k = 0; k < HD; k++){
            float4 w4 = *(const float4*)&sW[k*64 + tc*4];
            #pragma unroll
            for(int ri = 0; ri < 4; ri++){
                float a = sAg[(tr*4 + ri)*65 + k];
                acc[ri][0] += a*w4.x; acc[ri][1] += a*w4.y;
                acc[ri][2] += a*w4.z; acc[ri][3] += a*w4.w;
            }
        }
        float b2v[4];
        #pragma unroll
        for(int j = 0; j < 4; j++) b2v[j] = cb2[(l*3 + g)*HD + tc*4 + j];
        #pragma unroll
        for(int ri = 0; ri < 4; ri++)
            #pragma unroll
            for(int j = 0; j < 4; j++)
                sT[(tr*4 + ri)*65 + tc*4 + j] = sspf(acc[ri][j] + b2v[j]);
        __syncthreads();

        const float* w2 = bw + (l*3 + g)*HD*HD;
        for(int i = t; i < HD*HD; i += 128) sW[i] = w2[i];
        __syncthreads();

        for(int k = 0; k < HD; k++){
            float4 w4 = *(const float4*)&sW[k*64 + tc*4];
            #pragma unroll
            for(int ri = 0; ri < 4; ri++){
                float a = sT[(tr*4 + ri)*65 + k];
                hacc[ri][0] += a*w4.x; hacc[ri][1] += a*w4.y;
                hacc[ri][2] += a*w4.z; hacc[ri][3] += a*w4.w;
            }
        }
        float bbv[4];
        #pragma unroll
        for(int j = 0; j < 4; j++) bbv[j] = bb[(l*3 + g)*HD + tc*4 + j];
        #pragma unroll
        for(int ri = 0; ri < 4; ri++)
            #pragma unroll
            for(int j = 0; j < 4; j++) hacc[ri][j] += bbv[j];
        __syncthreads();
    }

    #pragma unroll
    for(int ri = 0; ri < 4; ri++){
        int row = r0 + tr*4 + ri;
        float4* hp = (float4*)&g_h[row*HD + tc*4];
        float4 hv = *hp;
        hv.x += hacc[ri][0]; hv.y += hacc[ri][1];
        hv.z += hacc[ri][2]; hv.w += hacc[ri][3];
        *hp = hv;
    }
}

__global__ void k_readout(const float* __restrict__ ow1, const float* __restrict__ ob1,
                          const float* __restrict__ ow2, const float* __restrict__ ob2,
                          float* __restrict__ out){
    __shared__ float sS[NB*HD];
    __shared__ float sV[NB*32];
    int t = threadIdx.x;
    int b = t >> 6, f = t & 63;
    float s = 0.0f;
    const float* hp = g_h + (size_t)(b*ATN + M1N)*HD + f;
    #pragma unroll 4
    for(int i = 0; i < M2N; i++) s += hp[(size_t)i*HD];
    sS[b*HD + f] = s;
    __syncthreads();
    if(t < NB*32){
        int b2 = t >> 5, j = t & 31;
        float v = 0.0f;
        #pragma unroll 8
        for(int f2 = 0; f2 < HD; f2++) v += sS[b2*HD + f2] * ow1[f2*32 + j];
        sV[b2*32 + j] = v + (float)M2N * ob1[j];
    }
    __syncthreads();
    if(t < NB){
        float o = 0.0f;
        #pragma unroll
        for(int j = 0; j < 32; j++) o += sV[t*32 + j] * ow2[j];
        out[t] = o + (float)M2N * ob2[0];
    }
}

extern "C" void kernel_launch(void* const* d_in, const int* in_sizes, int n_in,
                              void* d_out, int out_size){
    (void)in_sizes; (void)n_in; (void)out_size;
    const int*   sites  = (const int*)d_in[0];
    const int*   sitesp = (const int*)d_in[1];
    const int*   ei1 = (const int*)d_in[2];
    const float* ew1 = (const float*)d_in[3];
    const int*   c1  = (const int*)d_in[4];
    const int*   ei2 = (const int*)d_in[5];
    const float* ew2 = (const float*)d_in[6];
    const int*   c2  = (const int*)d_in[7];
    const int*   ei3 = (const int*)d_in[8];
    const float* ew3 = (const float*)d_in[9];
    const int*   c3  = (const int*)d_in[10];
    const float* embw  = (const float*)d_in[11];
    const float* embpw = (const float*)d_in[12];
    const float* mw1 = (const float*)d_in[13];
    const float* mb1 = (const float*)d_in[14];
    const float* mw2 = (const float*)d_in[15];
    const float* mb2 = (const float*)d_in[16];
    const float* cw1 = (const float*)d_in[17];
    const float* cw2 = (const float*)d_in[18];
    const float* cb2 = (const float*)d_in[19];
    const float* bw  = (const float*)d_in[20];
    const float* bb  = (const float*)d_in[21];
    const float* ow1 = (const float*)d_in[22];
    const float* ob1 = (const float*)d_in[23];
    const float* ow2 = (const float*)d_in[24];
    const float* ob2 = (const float*)d_in[25];
    float* out = (float*)d_out;

    k_count<<<(ETN + 255)/256, 256>>>(ei1, ei2, ei3, ew1, ew2, ew3, c1, c2, c3); // 1
    k_cbase_rs<<<3, 32>>>();                                                     // 2
    k_fill<<<(ETN + 255)/256, 256>>>(ei1, ei2, ei3, ew1, ew2, ew3, c1, c2, c3);  // 3

    dim3 gw0((E1N + 63)/64, CN, LN);
    dim3 gw1((E2N + 63)/64, CN, LN);
    dim3 gw2((E3N + 63)/64, CN, LN);
    k_wmlp<<<gw0, 128>>>(mw1, mb1, mw2, mb2, 0, 0, E1N);                         // 4 <- profiled
    k_wmlp<<<gw1, 128>>>(mw1, mb1, mw2, mb2, 1, E1N, E2N);
    k_wmlp<<<gw2, 128>>>(mw1, mb1, mw2, mb2, 2, E1N + E2N, E3N);
    k_embed<<<(NN*HD + 255)/256, 256>>>(sites, sitesp, embw, embpw);

    for(int l = 0; l < LN; l++){
        k_lin1<<<dim3(NN/64, 3), 128>>>(cw1, l);
        k_agg<<<dim3(ATN/8, 3), 256>>>(l);
        k_block<<<NN/32, 128>>>(cw2, cb2, bw, bb, l);
    }
    k_readout<<<1, 512>>>(ow1, ob1, ow2, ob2, out);
    k_cleanup<<<(3*ATN + 255)/256, 256>>>();
}

// round 12
// speedup vs baseline: 1.3532x; 1.0242x over previous
#include <cuda_runtime.h>
#include <math.h>

#define NB 8
#define M1N 2000
#define M2N 400
#define ATN 2400
#define NN (NB*ATN)
#define HD 64
#define NGN 50
#define NBUK 50
#define LN 4
#define CN 4
#define E1N 60000
#define E2N 20000
#define E3N 20000
#define ETN 100000

typedef unsigned long long u64;

__device__ float g_h[NN*HD];
__device__ float g_x[3][NN*HD];
__device__ float g_agg[3][NN*HD];
__device__ float g_W[LN*ETN*HD];
__device__ float g_d[ETN];
__device__ float g_ccut[ETN];
__device__ int   g_kq[ETN];
__device__ int   g_csrsrc[ETN];
__device__ int   g_csrw[ETN];
__device__ int   g_cnt[3*ATN];        // zero-init; re-zeroed by k_cleanup
__device__ int   g_cur[3*ATN];
__device__ int   g_rs[3*(ATN+1)];
__device__ int   g_cc2[3*CN*NBUK];
__device__ int   g_ccur2[3*CN*NBUK];
__device__ int   g_cb2[3*CN*NBUK];

__device__ __forceinline__ float sspf(float x){
    return fmaxf(x, 0.0f) + log1pf(__expf(-fabsf(x))) - 0.6931471805599453f;
}

__device__ __forceinline__ void fma2(u64& d, u64 a, u64 b){
    asm("fma.rn.f32x2 %0, %1, %2, %0;" : "+l"(d) : "l"(a), "l"(b));
}

__device__ __forceinline__ int bucket_of(float d){
    int b = (int)(d * 4.9f);
    return min(NBUK-1, max(0, b));
}

__device__ __forceinline__ void resolve_edge(int idx, int& g, int& e, int& eofs){
    if(idx < E1N){ g = 0; e = idx; eofs = 0; }
    else if(idx < E1N+E2N){ g = 1; e = idx-E1N; eofs = E1N; }
    else { g = 2; e = idx-E1N-E2N; eofs = E1N+E2N; }
}

// ---------------- preprocessing ----------------
__global__ void k_count(const int* __restrict__ e1, const int* __restrict__ e2,
                        const int* __restrict__ e3,
                        const float* __restrict__ w1, const float* __restrict__ w2,
                        const float* __restrict__ w3,
                        const int* __restrict__ c1, const int* __restrict__ c2,
                        const int* __restrict__ c3){
    int idx = blockIdx.x*blockDim.x + threadIdx.x;
    if(idx >= ETN) return;
    int g, e, eofs; resolve_edge(idx, g, e, eofs);
    const int* cp  = (g==0) ? c1 : ((g==1) ? c2 : c3);
    const int* eip = (g==0) ? e1 : ((g==1) ? e2 : e3);
    const float* wp = (g==0) ? w1 : ((g==1) ? w2 : w3);
    int b = bucket_of(wp[e]);
    atomicAdd(&g_cc2[(g*CN + cp[e])*NBUK + b], 1);
    atomicAdd(&g_cnt[g*ATN + eip[2*e + 1]], 1);
}

__global__ void k_cbase_rs(){
    int g = blockIdx.x;
    int lane = threadIdx.x;
    {
        const int per = ATN / 32;
        int base = lane * per;
        int sum = 0;
        for(int i = 0; i < per; i++) sum += g_cnt[g*ATN + base + i];
        int incl = sum;
        #pragma unroll
        for(int o = 1; o < 32; o <<= 1){
            int v = __shfl_up_sync(0xFFFFFFFFu, incl, o);
            if(lane >= o) incl += v;
        }
        int run = incl - sum;
        for(int i = 0; i < per; i++){
            g_rs[g*(ATN+1) + base + i] = run;
            run += g_cnt[g*ATN + base + i];
        }
        if(lane == 31) g_rs[g*(ATN+1) + ATN] = run;
    }
    {
        const int M = CN*NBUK;
        const int per = (M + 31) / 32;
        int base = lane * per;
        int sum = 0;
        for(int i = 0; i < per; i++){
            int id = base + i;
            if(id < M) sum += g_cc2[g*M + id];
        }
        int incl = sum;
        #pragma unroll
        for(int o = 1; o < 32; o <<= 1){
            int v = __shfl_up_sync(0xFFFFFFFFu, incl, o);
            if(lane >= o) incl += v;
        }
        int run = incl - sum;
        for(int i = 0; i < per; i++){
            int id = base + i;
            if(id < M){ g_cb2[g*M + id] = run; run += g_cc2[g*M + id]; }
        }
    }
}

__global__ void k_fill(const int* __restrict__ e1, const int* __restrict__ e2,
                       const int* __restrict__ e3,
                       const float* __restrict__ w1, const float* __restrict__ w2,
                       const float* __restrict__ w3,
                       const int* __restrict__ c1, const int* __restrict__ c2,
                       const int* __restrict__ c3){
    int idx = blockIdx.x*blockDim.x + threadIdx.x;
    if(idx >= ETN) return;
    int g, e, eofs; resolve_edge(idx, g, e, eofs);
    const int* cp  = (g==0) ? c1 : ((g==1) ? c2 : c3);
    const int* eip = (g==0) ? e1 : ((g==1) ? e2 : e3);
    const float* wp = (g==0) ? w1 : ((g==1) ? w2 : w3);
    int col = cp[e];
    float d = wp[e];
    int b = bucket_of(d);
    int slot = (g*CN + col)*NBUK + b;
    int p = g_cb2[slot] + atomicAdd(&g_ccur2[slot], 1);
    g_kq[eofs + p] = b;
    g_d[eofs + p] = d;
    g_ccut[eofs + p] = 0.5f * (cosf(d * 3.14159265358979323846f / 10.0f) + 1.0f);
    int src = eip[2*e], dst = eip[2*e + 1];
    int pc = g_rs[g*(ATN+1) + dst] + atomicAdd(&g_cur[g*ATN + dst], 1);
    g_csrsrc[eofs + pc] = src;
    g_csrw[eofs + pc] = p;
}

__global__ void k_embed(const int* __restrict__ sites, const int* __restrict__ sitesp,
                        const float* __restrict__ embw, const float* __restrict__ embpw){
    int idx = blockIdx.x*blockDim.x + threadIdx.x;
    if(idx >= NN*HD) return;
    int n = idx >> 6, f = idx & 63;
    int b = n / ATN, i = n - b*ATN;
    float v;
    if(i < M1N) v = embw[sites[b*M1N + i]*HD + f];
    else        v = embpw[sitesp[b*M2N + (i - M1N)]*HD + f];
    g_h[idx] = v;
}

__global__ void k_cleanup(){
    int i = blockIdx.x*blockDim.x + threadIdx.x;
    if(i < 3*ATN){ g_cnt[i] = 0; g_cur[i] = 0; }
    if(i < 3*CN*NBUK){ g_cc2[i] = 0; g_ccur2[i] = 0; }
}

// ---------------- edge-filter MLP: windowed GEMM-1 (attr on the fly) + f2 GEMM-2 ----
__global__ void k_wmlp(const float* __restrict__ mw1, const float* __restrict__ mb1,
                       const float* __restrict__ mw2, const float* __restrict__ mb2,
                       int g, int eofs, int etot){
    const int c = blockIdx.y, l = blockIdx.z;
    const int cb = g_cb2[(g*CN + c)*NBUK];
    const int ce = (c == CN-1) ? etot : g_cb2[(g*CN + c + 1)*NBUK];
    const int r0 = cb + blockIdx.x*64;
    if(r0 >= ce) return;
    const int t = threadIdx.x;
    const int tc = t & 15, tr = t >> 4;

    __shared__ __align__(16) float sW[64*64];
    __shared__ __align__(16) float sU[64*66];   // attr window, then H tile

    const int b0 = g_kq[eofs + r0];
    const int b1 = g_kq[eofs + min(r0 + 63, ce - 1)];
    const int k0 = max(0, b0 - 6);
    const int kend = min(NGN - 1, b1 + 7);
    const int Wd = kend - k0 + 1;

    const int pgc = (l*3 + g)*CN + c;
    const float* w1 = mw1 + pgc*NGN*HD;
    for(int i = t; i < NGN*HD; i += 128) sW[i] = w1[i];
    {
        const float step = 10.0f / 49.0f;
        const float coeff = -0.5f / (step*step);
        int total = 64 * Wd;
        for(int i = t; i < total; i += 128){
            int rr = i / Wd;
            int kk = k0 + (i - rr*Wd);
            int row = r0 + rr;
            float v = 0.0f;
            if(row < ce){
                float d = __ldg(&g_d[eofs + row]);
                float tt = d - step * (float)kk;
                v = __expf(coeff * tt * tt);
            }
            sU[rr*66 + kk] = v;
        }
    }
    __syncthreads();

    float acc[8][4];
    #pragma unroll
    for(int ri = 0; ri < 8; ri++){ acc[ri][0]=0; acc[ri][1]=0; acc[ri][2]=0; acc[ri][3]=0; }
    for(int k = k0; k <= kend; k++){
        float4 w = *(const float4*)&sW[k*64 + tc*4];
        #pragma unroll
        for(int ri = 0; ri < 8; ri++){
            float a = sU[(tr*8 + ri)*66 + k];
            acc[ri][0] += a*w.x; acc[ri][1] += a*w.y;
            acc[ri][2] += a*w.z; acc[ri][3] += a*w.w;
        }
    }
    __syncthreads();

    float b1v[4];
    #pragma unroll
    for(int j = 0; j < 4; j++) b1v[j] = mb1[pgc*HD + tc*4 + j];
    #pragma unroll
    for(int ri = 0; ri < 8; ri++)
        #pragma unroll
        for(int j = 0; j < 4; j++)
            sU[(tr*8 + ri)*66 + tc*4 + j] = sspf(acc[ri][j] + b1v[j]);
    const float* w2 = mw2 + pgc*HD*HD;
    for(int i = t; i < HD*HD; i += 128) sW[i] = w2[i];
    __syncthreads();

    float acc2[8][4];
    #pragma unroll
    for(int ri = 0; ri < 8; ri++){ acc2[ri][0]=0; acc2[ri][1]=0; acc2[ri][2]=0; acc2[ri][3]=0; }
    for(int k = 0; k < HD; k += 2){
        float4 wa = *(const float4*)&sW[k*64 + tc*4];
        float4 wb = *(const float4*)&sW[(k+1)*64 + tc*4];
        #pragma unroll
        for(int ri = 0; ri < 8; ri++){
            float2 a = *(const float2*)&sU[(tr*8 + ri)*66 + k];
            acc2[ri][0] += a.x*wa.x; acc2[ri][1] += a.x*wa.y;
            acc2[ri][2] += a.x*wa.z; acc2[ri][3] += a.x*wa.w;
            acc2[ri][0] += a.y*wb.x; acc2[ri][1] += a.y*wb.y;
            acc2[ri][2] += a.y*wb.z; acc2[ri][3] += a.y*wb.w;
        }
    }
    float b2v[4];
    #pragma unroll
    for(int j = 0; j < 4; j++) b2v[j] = mb2[pgc*HD + tc*4 + j];
    #pragma unroll
    for(int ri = 0; ri < 8; ri++){
        int row = r0 + tr*8 + ri;
        if(row < ce){
            float cc = g_ccut[eofs + row];
            float4 o;
            o.x = (acc2[ri][0] + b2v[0]) * cc;
            o.y = (acc2[ri][1] + b2v[1]) * cc;
            o.z = (acc2[ri][2] + b2v[2]) * cc;
            o.w = (acc2[ri][3] + b2v[3]) * cc;
            *(float4*)&g_W[(size_t)(l*ETN + eofs + row)*HD + tc*4] = o;
        }
    }
}

// ---------------- lin1 (pad 66, f2 k-pairs) ----------------
__global__ void k_lin1(const float* __restrict__ cw1, int l){
    const int gph = blockIdx.y;
    const int r0 = blockIdx.x * 64;
    const int t = threadIdx.x, tc = t & 15, tr = t >> 4;
    __shared__ __align__(16) float sW[64*64];
    __shared__ __align__(16) float sHt[64*66];
    const float* w = cw1 + (l*3 + gph)*HD*HD;
    for(int i = t; i < HD*HD; i += 128) sW[i] = w[i];
    for(int i = t; i < 64*64; i += 128){
        int rr = i >> 6, kk = i & 63;
        sHt[rr*66 + kk] = g_h[(r0 + rr)*HD + kk];
    }
    __syncthreads();
    float acc[8][4];
    #pragma unroll
    for(int ri = 0; ri < 8; ri++){ acc[ri][0]=0; acc[ri][1]=0; acc[ri][2]=0; acc[ri][3]=0; }
    for(int k = 0; k < HD; k += 2){
        float4 wa = *(const float4*)&sW[k*64 + tc*4];
        float4 wb = *(const float4*)&sW[(k+1)*64 + tc*4];
        #pragma unroll
        for(int ri = 0; ri < 8; ri++){
            float2 a = *(const float2*)&sHt[(tr*8 + ri)*66 + k];
            acc[ri][0] += a.x*wa.x; acc[ri][1] += a.x*wa.y;
            acc[ri][2] += a.x*wa.z; acc[ri][3] += a.x*wa.w;
            acc[ri][0] += a.y*wb.x; acc[ri][1] += a.y*wb.y;
            acc[ri][2] += a.y*wb.z; acc[ri][3] += a.y*wb.w;
        }
    }
    float* xo = g_x[gph];
    #pragma unroll
    for(int ri = 0; ri < 8; ri++){
        int row = r0 + tr*8 + ri;
        float4 o; o.x = acc[ri][0]; o.y = acc[ri][1]; o.z = acc[ri][2]; o.w = acc[ri][3];
        *(float4*)&xo[row*HD + tc*4] = o;
    }
}

// ---------------- CSR aggregation (R9 form) ----------------
__global__ void k_agg(int l){
    const int gph = blockIdx.y;
    const int t = threadIdx.x;
    const int f2 = t & 31;
    const int dq = t >> 5;
    const int dst = blockIdx.x*8 + dq;
    const int eofs = (gph == 0) ? 0 : ((gph == 1) ? E1N : (E1N + E2N));
    const int s = g_rs[gph*(ATN+1) + dst];
    const int e = g_rs[gph*(ATN+1) + dst + 1];
    const u64* __restrict__ xq = (const u64*)g_x[gph];
    const u64* __restrict__ Wq = (const u64*)(g_W + (size_t)l*ETN*HD) + (size_t)eofs*32;
    u64 acc[NB];
    #pragma unroll
    for(int b = 0; b < NB; b++) acc[b] = 0ull;
    int src = 0, wp = 0;
    if(s < e){ src = __ldg(&g_csrsrc[eofs + s]); wp = __ldg(&g_csrw[eofs + s]); }
    for(int p = s; p < e; p++){
        int ns = 0, nw = 0;
        if(p + 1 < e){ ns = __ldg(&g_csrsrc[eofs + p + 1]); nw = __ldg(&g_csrw[eofs + p + 1]); }
        u64 w = Wq[(size_t)wp*32 + f2];
        int base = src*32 + f2;
        #pragma unroll
        for(int b = 0; b < NB; b++)
            fma2(acc[b], xq[base + b*ATN*32], w);
        src = ns; wp = nw;
    }
    u64* aq = (u64*)g_agg[gph];
    int ob = dst*32 + f2;
    #pragma unroll
    for(int b = 0; b < NB; b++)
        aq[ob + b*ATN*32] = acc[b];
}

// ---------------- block (32-row, pad 66, f2 k-pairs) ----------------
__global__ void k_block(const float* __restrict__ cw2, const float* __restrict__ cb2,
                        const float* __restrict__ bw, const float* __restrict__ bb,
                        int l){
    const int r0 = blockIdx.x * 32;
    const int t = threadIdx.x, tc = t & 15, tr = t >> 4;
    __shared__ __align__(16) float sW[64*64];
    __shared__ __align__(16) float sAg[32*66];
    __shared__ __align__(16) float sT[32*66];
    float hacc[4][4];
    #pragma unroll
    for(int ri = 0; ri < 4; ri++){ hacc[ri][0]=0; hacc[ri][1]=0; hacc[ri][2]=0; hacc[ri][3]=0; }

    for(int g = 0; g < 3; g++){
        const float* w = cw2 + (l*3 + g)*HD*HD;
        for(int i = t; i < HD*HD; i += 128) sW[i] = w[i];
        const float* ag = g_agg[g];
        for(int i = t; i < 32*64; i += 128){
            int rr = i >> 6, kk = i & 63;
            sAg[rr*66 + kk] = ag[(r0 + rr)*HD + kk];
        }
        __syncthreads();

        float acc[4][4];
        #pragma unroll
        for(int ri = 0; ri < 4; ri++){ acc[ri][0]=0; acc[ri][1]=0; acc[ri][2]=0; acc[ri][3]=0; }
        for(int k = 0; k < HD; k += 2){
            float4 wa = *(const float4*)&sW[k*64 + tc*4];
            float4 wb = *(const float4*)&sW[(k+1)*64 + tc*4];
            #pragma unroll
            for(int ri = 0; ri < 4; ri++){
                float2 a = *(const float2*)&sAg[(tr*4 + ri)*66 + k];
                acc[ri][0] += a.x*wa.x; acc[ri][1] += a.x*wa.y;
                acc[ri][2] += a.x*wa.z; acc[ri][3] += a.x*wa.w;
                acc[ri][0] += a.y*wb.x; acc[ri][1] += a.y*wb.y;
                acc[ri][2] += a.y*wb.z; acc[ri][3] += a.y*wb.w;
            }
        }
        float b2v[4];
        #pragma unroll
        for(int j = 0; j < 4; j++) b2v[j] = cb2[(l*3 + g)*HD + tc*4 + j];
        #pragma unroll
        for(int ri = 0; ri < 4; ri++)
            #pragma unroll
            for(int j = 0; j < 4; j++)
                sT[(tr*4 + ri)*66 + tc*4 + j] = sspf(acc[ri][j] + b2v[j]);
        __syncthreads();

        const float* w2 = bw + (l*3 + g)*HD*HD;
        for(int i = t; i < HD*HD; i += 128) sW[i] = w2[i];
        __syncthreads();

        for(int k = 0; k < HD; k += 2){
            float4 wa = *(const float4*)&sW[k*64 + tc*4];
            float4 wb = *(const float4*)&sW[(k+1)*64 + tc*4];
            #pragma unroll
            for(int ri = 0; ri < 4; ri++){
                float2 a = *(const float2*)&sT[(tr*4 + ri)*66 + k];
                hacc[ri][0] += a.x*wa.x; hacc[ri][1] += a.x*wa.y;
                hacc[ri][2] += a.x*wa.z; hacc[ri][3] += a.x*wa.w;
                hacc[ri][0] += a.y*wb.x; hacc[ri][1] += a.y*wb.y;
                hacc[ri][2] += a.y*wb.z; hacc[ri][3] += a.y*wb.w;
            }
        }
        float bbv[4];
        #pragma unroll
        for(int j = 0; j < 4; j++) bbv[j] = bb[(l*3 + g)*HD + tc*4 + j];
        #pragma unroll
        for(int ri = 0; ri < 4; ri++)
            #pragma unroll
            for(int j = 0; j < 4; j++) hacc[ri][j] += bbv[j];
        __syncthreads();
    }

    #pragma unroll
    for(int ri = 0; ri < 4; ri++){
        int row = r0 + tr*4 + ri;
        float4* hp = (float4*)&g_h[row*HD + tc*4];
        float4 hv = *hp;
        hv.x += hacc[ri][0]; hv.y += hacc[ri][1];
        hv.z += hacc[ri][2]; hv.w += hacc[ri][3];
        *hp = hv;
    }
}

__global__ void k_readout(const float* __restrict__ ow1, const float* __restrict__ ob1,
                          const float* __restrict__ ow2, const float* __restrict__ ob2,
                          float* __restrict__ out){
    __shared__ float sS[NB*HD];
    __shared__ float sV[NB*32];
    int t = threadIdx.x;
    int b = t >> 6, f = t & 63;
    float s = 0.0f;
    const float* hp = g_h + (size_t)(b*ATN + M1N)*HD + f;
    #pragma unroll 4
    for(int i = 0; i < M2N; i++) s += hp[(size_t)i*HD];
    sS[b*HD + f] = s;
    __syncthreads();
    if(t < NB*32){
        int b2 = t >> 5, j = t & 31;
        float v = 0.0f;
        #pragma unroll 8
        for(int f2 = 0; f2 < HD; f2++) v += sS[b2*HD + f2] * ow1[f2*32 + j];
        sV[b2*32 + j] = v + (float)M2N * ob1[j];
    }
    __syncthreads();
    if(t < NB){
        float o = 0.0f;
        #pragma unroll
        for(int j = 0; j < 32; j++) o += sV[t*32 + j] * ow2[j];
        out[t] = o + (float)M2N * ob2[0];
    }
}

extern "C" void kernel_launch(void* const* d_in, const int* in_sizes, int n_in,
                              void* d_out, int out_size){
    (void)in_sizes; (void)n_in; (void)out_size;
    const int*   sites  = (const int*)d_in[0];
    const int*   sitesp = (const int*)d_in[1];
    const int*   ei1 = (const int*)d_in[2];
    const float* ew1 = (const float*)d_in[3];
    const int*   c1  = (const int*)d_in[4];
    const int*   ei2 = (const int*)d_in[5];
    const float* ew2 = (const float*)d_in[6];
    const int*   c2  = (const int*)d_in[7];
    const int*   ei3 = (const int*)d_in[8];
    const float* ew3 = (const float*)d_in[9];
    const int*   c3  = (const int*)d_in[10];
    const float* embw  = (const float*)d_in[11];
    const float* embpw = (const float*)d_in[12];
    const float* mw1 = (const float*)d_in[13];
    const float* mb1 = (const float*)d_in[14];
    const float* mw2 = (const float*)d_in[15];
    const float* mb2 = (const float*)d_in[16];
    const float* cw1 = (const float*)d_in[17];
    const float* cw2 = (const float*)d_in[18];
    const float* cb2 = (const float*)d_in[19];
    const float* bw  = (const float*)d_in[20];
    const float* bb  = (const float*)d_in[21];
    const float* ow1 = (const float*)d_in[22];
    const float* ob1 = (const float*)d_in[23];
    const float* ow2 = (const float*)d_in[24];
    const float* ob2 = (const float*)d_in[25];
    float* out = (float*)d_out;

    k_count<<<(ETN + 255)/256, 256>>>(ei1, ei2, ei3, ew1, ew2, ew3, c1, c2, c3); // 1
    k_cbase_rs<<<3, 32>>>();                                                     // 2
    k_fill<<<(ETN + 255)/256, 256>>>(ei1, ei2, ei3, ew1, ew2, ew3, c1, c2, c3);  // 3

    dim3 gw0((E1N + 63)/64, CN, LN);
    dim3 gw1((E2N + 63)/64, CN, LN);
    dim3 gw2((E3N + 63)/64, CN, LN);
    k_wmlp<<<gw0, 128>>>(mw1, mb1, mw2, mb2, 0, 0, E1N);                         // 4 <- profiled
    k_wmlp<<<gw1, 128>>>(mw1, mb1, mw2, mb2, 1, E1N, E2N);
    k_wmlp<<<gw2, 128>>>(mw1, mb1, mw2, mb2, 2, E1N + E2N, E3N);
    k_embed<<<(NN*HD + 255)/256, 256>>>(sites, sitesp, embw, embpw);

    for(int l = 0; l < LN; l++){
        k_lin1<<<dim3(NN/64, 3), 128>>>(cw1, l);
        k_agg<<<dim3(ATN/8, 3), 256>>>(l);
        k_block<<<NN/32, 128>>>(cw2, cb2, bw, bb, l);
    }
    k_readout<<<1, 512>>>(ow1, ob1, ow2, ob2, out);
    k_cleanup<<<(3*ATN + 255)/256, 256>>>();
}

// round 14
// speedup vs baseline: 1.3572x; 1.0030x over previous
#include <cuda_runtime.h>
#include <math.h>

#define NB 8
#define M1N 2000
#define M2N 400
#define ATN 2400
#define NN (NB*ATN)
#define HD 64
#define NGN 50
#define NBUK 50
#define LN 4
#define CN 4
#define E1N 60000
#define E2N 20000
#define E3N 20000
#define ETN 100000

typedef unsigned long long u64;

__device__ float g_h[NN*HD];
__device__ float g_x[3][NN*HD];
__device__ float g_agg[3][NN*HD];
__device__ float g_W[LN*ETN*HD];
__device__ float g_d[ETN];
__device__ float g_ccut[ETN];
__device__ int   g_kq[ETN];
__device__ int2  g_csr[ETN];
__device__ int   g_cnt[3*ATN];        // zero-init; re-zeroed by k_cleanup
__device__ int   g_cur[3*ATN];
__device__ int   g_rs[3*(ATN+1)];
__device__ int   g_cc2[3*CN*NBUK];
__device__ int   g_ccur2[3*CN*NBUK];
__device__ int   g_cb2[3*CN*NBUK];

__device__ __forceinline__ float sspf(float x){
    return fmaxf(x, 0.0f) + log1pf(__expf(-fabsf(x))) - 0.6931471805599453f;
}

__device__ __forceinline__ void fma2(u64& d, u64 a, u64 b){
    asm("fma.rn.f32x2 %0, %1, %2, %0;" : "+l"(d) : "l"(a), "l"(b));
}

__device__ __forceinline__ int bucket_of(float d){
    int b = (int)(d * 4.9f);
    return min(NBUK-1, max(0, b));
}

__device__ __forceinline__ void resolve_edge(int idx, int& g, int& e, int& eofs){
    if(idx < E1N){ g = 0; e = idx; eofs = 0; }
    else if(idx < E1N+E2N){ g = 1; e = idx-E1N; eofs = E1N; }
    else { g = 2; e = idx-E1N-E2N; eofs = E1N+E2N; }
}

// ---------------- preprocessing ----------------
__global__ void k_count(const int* __restrict__ e1, const int* __restrict__ e2,
                        const int* __restrict__ e3,
                        const float* __restrict__ w1, const float* __restrict__ w2,
                        const float* __restrict__ w3,
                        const int* __restrict__ c1, const int* __restrict__ c2,
                        const int* __restrict__ c3){
    int idx = blockIdx.x*blockDim.x + threadIdx.x;
    if(idx >= ETN) return;
    int g, e, eofs; resolve_edge(idx, g, e, eofs);
    const int* cp  = (g==0) ? c1 : ((g==1) ? c2 : c3);
    const int* eip = (g==0) ? e1 : ((g==1) ? e2 : e3);
    const float* wp = (g==0) ? w1 : ((g==1) ? w2 : w3);
    int b = bucket_of(wp[e]);
    atomicAdd(&g_cc2[(g*CN + cp[e])*NBUK + b], 1);
    atomicAdd(&g_cnt[g*ATN + eip[2*e + 1]], 1);
}

__global__ void k_cbase_rs(){
    int g = blockIdx.x;
    int lane = threadIdx.x;
    {
        const int per = ATN / 32;
        int base = lane * per;
        int sum = 0;
        for(int i = 0; i < per; i++) sum += g_cnt[g*ATN + base + i];
        int incl = sum;
        #pragma unroll
        for(int o = 1; o < 32; o <<= 1){
            int v = __shfl_up_sync(0xFFFFFFFFu, incl, o);
            if(lane >= o) incl += v;
        }
        int run = incl - sum;
        for(int i = 0; i < per; i++){
            g_rs[g*(ATN+1) + base + i] = run;
            run += g_cnt[g*ATN + base + i];
        }
        if(lane == 31) g_rs[g*(ATN+1) + ATN] = run;
    }
    {
        const int M = CN*NBUK;
        const int per = (M + 31) / 32;
        int base = lane * per;
        int sum = 0;
        for(int i = 0; i < per; i++){
            int id = base + i;
            if(id < M) sum += g_cc2[g*M + id];
        }
        int incl = sum;
        #pragma unroll
        for(int o = 1; o < 32; o <<= 1){
            int v = __shfl_up_sync(0xFFFFFFFFu, incl, o);
            if(lane >= o) incl += v;
        }
        int run = incl - sum;
        for(int i = 0; i < per; i++){
            int id = base + i;
            if(id < M){ g_cb2[g*M + id] = run; run += g_cc2[g*M + id]; }
        }
    }
}

__global__ void k_fill(const int* __restrict__ e1, const int* __restrict__ e2,
                       const int* __restrict__ e3,
                       const float* __restrict__ w1, const float* __restrict__ w2,
                       const float* __restrict__ w3,
                       const int* __restrict__ c1, const int* __restrict__ c2,
                       const int* __restrict__ c3){
    int idx = blockIdx.x*blockDim.x + threadIdx.x;
    if(idx >= ETN) return;
    int g, e, eofs; resolve_edge(idx, g, e, eofs);
    const int* cp  = (g==0) ? c1 : ((g==1) ? c2 : c3);
    const int* eip = (g==0) ? e1 : ((g==1) ? e2 : e3);
    const float* wp = (g==0) ? w1 : ((g==1) ? w2 : w3);
    int col = cp[e];
    float d = wp[e];
    int b = bucket_of(d);
    int slot = (g*CN + col)*NBUK + b;
    int p = g_cb2[slot] + atomicAdd(&g_ccur2[slot], 1);
    g_kq[eofs + p] = b;
    g_d[eofs + p] = d;
    g_ccut[eofs + p] = 0.5f * (cosf(d * 3.14159265358979323846f / 10.0f) + 1.0f);
    int src = eip[2*e], dst = eip[2*e + 1];
    int pc = g_rs[g*(ATN+1) + dst] + atomicAdd(&g_cur[g*ATN + dst], 1);
    g_csr[eofs + pc] = make_int2(src, p);
}

__global__ void k_embed(const int* __restrict__ sites, const int* __restrict__ sitesp,
                        const float* __restrict__ embw, const float* __restrict__ embpw){
    int idx = blockIdx.x*blockDim.x + threadIdx.x;
    if(idx >= NN*HD) return;
    int n = idx >> 6, f = idx & 63;
    int b = n / ATN, i = n - b*ATN;
    float v;
    if(i < M1N) v = embw[sites[b*M1N + i]*HD + f];
    else        v = embpw[sitesp[b*M2N + (i - M1N)]*HD + f];
    g_h[idx] = v;
}

__global__ void k_cleanup(){
    int i = blockIdx.x*blockDim.x + threadIdx.x;
    if(i < 3*ATN){ g_cnt[i] = 0; g_cur[i] = 0; }
    if(i < 3*CN*NBUK){ g_cc2[i] = 0; g_ccur2[i] = 0; }
}

// ---------------- edge-filter MLP: one launch (z = l*3+g), 32-row weight halves ----
__global__ void k_wmlp(const float* __restrict__ mw1, const float* __restrict__ mb1,
                       const float* __restrict__ mw2, const float* __restrict__ mb2){
    const int c = blockIdx.y;
    const int lz = blockIdx.z;
    const int l = lz / 3, g = lz - l*3;
    const int eofs = (g == 0) ? 0 : ((g == 1) ? E1N : (E1N + E2N));
    const int etot = (g == 0) ? E1N : ((g == 1) ? E2N : E3N);
    const int cb = g_cb2[(g*CN + c)*NBUK];
    const int ce = (c == CN-1) ? etot : g_cb2[(g*CN + c + 1)*NBUK];
    const int r0 = cb + blockIdx.x*64;
    if(r0 >= ce) return;
    const int t = threadIdx.x;
    const int tc = t & 15, tr = t >> 4;

    __shared__ __align__(16) float sW[32*64];   // 32-row weight half-tile (8KB)
    __shared__ __align__(16) float sU[64*66];   // attr window, then H tile

    const int b0 = g_kq[eofs + r0];
    const int b1 = g_kq[eofs + min(r0 + 63, ce - 1)];
    const int k0 = max(0, b0 - 6);
    const int kend = min(NGN - 1, b1 + 7);
    const int Wd = kend - k0 + 1;

    const int pgc = (l*3 + g)*CN + c;
    const float* w1 = mw1 + pgc*NGN*HD;
    // generate attr window on the fly (k0..kend only)
    {
        const float step = 10.0f / 49.0f;
        const float coeff = -0.5f / (step*step);
        int total = 64 * Wd;
        for(int i = t; i < total; i += 128){
            int rr = i / Wd;
            int kk = k0 + (i - rr*Wd);
            int row = r0 + rr;
            float v = 0.0f;
            if(row < ce){
                float d = __ldg(&g_d[eofs + row]);
                float tt = d - step * (float)kk;
                v = __expf(coeff * tt * tt);
            }
            sU[rr*66 + kk] = v;
        }
    }

    float acc[8][4];
    #pragma unroll
    for(int ri = 0; ri < 8; ri++){ acc[ri][0]=0; acc[ri][1]=0; acc[ri][2]=0; acc[ri][3]=0; }
    // GEMM-1 over window, weights streamed in <=32-row chunks
    for(int kb = k0; kb <= kend; kb += 32){
        int kh = min(kend, kb + 31);
        int nrows = kh - kb + 1;
        for(int i = t; i < nrows*HD; i += 128) sW[i] = w1[kb*HD + i];
        __syncthreads();
        for(int k = kb; k <= kh; k++){
            float4 w = *(const float4*)&sW[(k-kb)*64 + tc*4];
            #pragma unroll
            for(int ri = 0; ri < 8; ri++){
                float a = sU[(tr*8 + ri)*66 + k];
                acc[ri][0] += a*w.x; acc[ri][1] += a*w.y;
                acc[ri][2] += a*w.z; acc[ri][3] += a*w.w;
            }
        }
        __syncthreads();
    }

    float b1v[4];
    #pragma unroll
    for(int j = 0; j < 4; j++) b1v[j] = mb1[pgc*HD + tc*4 + j];
    #pragma unroll
    for(int ri = 0; ri < 8; ri++)
        #pragma unroll
        for(int j = 0; j < 4; j++)
            sU[(tr*8 + ri)*66 + tc*4 + j] = sspf(acc[ri][j] + b1v[j]);

    const float* w2 = mw2 + pgc*HD*HD;
    float acc2[8][4];
    #pragma unroll
    for(int ri = 0; ri < 8; ri++){ acc2[ri][0]=0; acc2[ri][1]=0; acc2[ri][2]=0; acc2[ri][3]=0; }
    // GEMM-2 in two 32-k halves
    for(int kb2 = 0; kb2 < HD; kb2 += 32){
        for(int i = t; i < 32*HD; i += 128) sW[i] = w2[kb2*HD + i];
        __syncthreads();
        #pragma unroll 4
        for(int kk = 0; kk < 32; kk += 2){
            float4 wa = *(const float4*)&sW[kk*64 + tc*4];
            float4 wb = *(const float4*)&sW[(kk+1)*64 + tc*4];
            #pragma unroll
            for(int ri = 0; ri < 8; ri++){
                float2 a = *(const float2*)&sU[(tr*8 + ri)*66 + kb2 + kk];
                acc2[ri][0] += a.x*wa.x; acc2[ri][1] += a.x*wa.y;
                acc2[ri][2] += a.x*wa.z; acc2[ri][3] += a.x*wa.w;
                acc2[ri][0] += a.y*wb.x; acc2[ri][1] += a.y*wb.y;
                acc2[ri][2] += a.y*wb.z; acc2[ri][3] += a.y*wb.w;
            }
        }
        __syncthreads();
    }
    float b2v[4];
    #pragma unroll
    for(int j = 0; j < 4; j++) b2v[j] = mb2[pgc*HD + tc*4 + j];
    #pragma unroll
    for(int ri = 0; ri < 8; ri++){
        int row = r0 + tr*8 + ri;
        if(row < ce){
            float cc = g_ccut[eofs + row];
            float4 o;
            o.x = (acc2[ri][0] + b2v[0]) * cc;
            o.y = (acc2[ri][1] + b2v[1]) * cc;
            o.z = (acc2[ri][2] + b2v[2]) * cc;
            o.w = (acc2[ri][3] + b2v[3]) * cc;
            *(float4*)&g_W[(size_t)(l*ETN + eofs + row)*HD + tc*4] = o;
        }
    }
}

// ---------------- lin1 (R12 form) ----------------
__global__ void k_lin1(const float* __restrict__ cw1, int l){
    const int gph = blockIdx.y;
    const int r0 = blockIdx.x * 64;
    const int t = threadIdx.x, tc = t & 15, tr = t >> 4;
    __shared__ __align__(16) float sW[64*64];
    __shared__ __align__(16) float sHt[64*66];
    const float* w = cw1 + (l*3 + gph)*HD*HD;
    for(int i = t; i < HD*HD; i += 128) sW[i] = w[i];
    for(int i = t; i < 64*64; i += 128){
        int rr = i >> 6, kk = i & 63;
        sHt[rr*66 + kk] = g_h[(r0 + rr)*HD + kk];
    }
    __syncthreads();
    float acc[8][4];
    #pragma unroll
    for(int ri = 0; ri < 8; ri++){ acc[ri][0]=0; acc[ri][1]=0; acc[ri][2]=0; acc[ri][3]=0; }
    for(int k = 0; k < HD; k += 2){
        float4 wa = *(const float4*)&sW[k*64 + tc*4];
        float4 wb = *(const float4*)&sW[(k+1)*64 + tc*4];
        #pragma unroll
        for(int ri = 0; ri < 8; ri++){
            float2 a = *(const float2*)&sHt[(tr*8 + ri)*66 + k];
            acc[ri][0] += a.x*wa.x; acc[ri][1] += a.x*wa.y;
            acc[ri][2] += a.x*wa.z; acc[ri][3] += a.x*wa.w;
            acc[ri][0] += a.y*wb.x; acc[ri][1] += a.y*wb.y;
            acc[ri][2] += a.y*wb.z; acc[ri][3] += a.y*wb.w;
        }
    }
    float* xo = g_x[gph];
    #pragma unroll
    for(int ri = 0; ri < 8; ri++){
        int row = r0 + tr*8 + ri;
        float4 o; o.x = acc[ri][0]; o.y = acc[ri][1]; o.z = acc[ri][2]; o.w = acc[ri][3];
        *(float4*)&xo[row*HD + tc*4] = o;
    }
}

// ---------------- CSR aggregation: int2 index stream + 2-edge unroll ----------------
__global__ void k_agg(int l){
    const int gph = blockIdx.y;
    const int t = threadIdx.x;
    const int f2 = t & 31;
    const int dq = t >> 5;
    const int dst = blockIdx.x*8 + dq;
    const int eofs = (gph == 0) ? 0 : ((gph == 1) ? E1N : (E1N + E2N));
    const int s = g_rs[gph*(ATN+1) + dst];
    const int e = g_rs[gph*(ATN+1) + dst + 1];
    const u64* __restrict__ xq = (const u64*)g_x[gph];
    const u64* __restrict__ Wq = (const u64*)(g_W + (size_t)l*ETN*HD) + (size_t)eofs*32;
    u64 acc[NB];
    #pragma unroll
    for(int b = 0; b < NB; b++) acc[b] = 0ull;
    int p = s;
    for(; p + 1 < e; p += 2){
        int2 c0 = __ldg(&g_csr[eofs + p]);
        int2 c1 = __ldg(&g_csr[eofs + p + 1]);
        u64 w0 = Wq[(size_t)c0.y*32 + f2];
        u64 w1 = Wq[(size_t)c1.y*32 + f2];
        int base0 = c0.x*32 + f2;
        int base1 = c1.x*32 + f2;
        #pragma unroll
        for(int b = 0; b < NB; b++){
            fma2(acc[b], xq[base0 + b*ATN*32], w0);
            fma2(acc[b], xq[base1 + b*ATN*32], w1);
        }
    }
    if(p < e){
        int2 c0 = __ldg(&g_csr[eofs + p]);
        u64 w0 = Wq[(size_t)c0.y*32 + f2];
        int base0 = c0.x*32 + f2;
        #pragma unroll
        for(int b = 0; b < NB; b++)
            fma2(acc[b], xq[base0 + b*ATN*32], w0);
    }
    u64* aq = (u64*)g_agg[gph];
    int ob = dst*32 + f2;
    #pragma unroll
    for(int b = 0; b < NB; b++)
        aq[ob + b*ATN*32] = acc[b];
}

// ---------------- block (R12 form) ----------------
__global__ void k_block(const float* __restrict__ cw2, const float* __restrict__ cb2,
                        const float* __restrict__ bw, const float* __restrict__ bb,
                        int l){
    const int r0 = blockIdx.x * 32;
    const int t = threadIdx.x, tc = t & 15, tr = t >> 4;
    __shared__ __align__(16) float sW[64*64];
    __shared__ __align__(16) float sAg[32*66];
    __shared__ __align__(16) float sT[32*66];
    float hacc[4][4];
    #pragma unroll
    for(int ri = 0; ri < 4; ri++){ hacc[ri][0]=0; hacc[ri][1]=0; hacc[ri][2]=0; hacc[ri][3]=0; }

    for(int g = 0; g < 3; g++){
        const float* w = cw2 + (l*3 + g)*HD*HD;
        for(int i = t; i < HD*HD; i += 128) sW[i] = w[i];
        const float* ag = g_agg[g];
        for(int i = t; i < 32*64; i += 128){
            int rr = i >> 6, kk = i & 63;
            sAg[rr*66 + kk] = ag[(r0 + rr)*HD + kk];
        }
        __syncthreads();

        float acc[4][4];
        #pragma unroll
        for(int ri = 0; ri < 4; ri++){ acc[ri][0]=0; acc[ri][1]=0; acc[ri][2]=0; acc[ri][3]=0; }
        for(int k = 0; k < HD; k += 2){
            float4 wa = *(const float4*)&sW[k*64 + tc*4];
            float4 wb = *(const float4*)&sW[(k+1)*64 + tc*4];
            #pragma unroll
            for(int ri = 0; ri < 4; ri++){
                float2 a = *(const float2*)&sAg[(tr*4 + ri)*66 + k];
                acc[ri][0] += a.x*wa.x; acc[ri][1] += a.x*wa.y;
                acc[ri][2] += a.x*wa.z; acc[ri][3] += a.x*wa.w;
                acc[ri][0] += a.y*wb.x; acc[ri][1] += a.y*wb.y;
                acc[ri][2] += a.y*wb.z; acc[ri][3] += a.y*wb.w;
            }
        }
        float b2v[4];
        #pragma unroll
        for(int j = 0; j < 4; j++) b2v[j] = cb2[(l*3 + g)*HD + tc*4 + j];
        #pragma unroll
        for(int ri = 0; ri < 4; ri++)
            #pragma unroll
            for(int j = 0; j < 4; j++)
                sT[(tr*4 + ri)*66 + tc*4 + j] = sspf(acc[ri][j] + b2v[j]);
        __syncthreads();

        const float* w2 = bw + (l*3 + g)*HD*HD;
        for(int i = t; i < HD*HD; i += 128) sW[i] = w2[i];
        __syncthreads();

        for(int k = 0; k < HD; k += 2){
            float4 wa = *(const float4*)&sW[k*64 + tc*4];
            float4 wb = *(const float4*)&sW[(k+1)*64 + tc*4];
            #pragma unroll
            for(int ri = 0; ri < 4; ri++){
                float2 a = *(const float2*)&sT[(tr*4 + ri)*66 + k];
                hacc[ri][0] += a.x*wa.x; hacc[ri][1] += a.x*wa.y;
                hacc[ri][2] += a.x*wa.z; hacc[ri][3] += a.x*wa.w;
                hacc[ri][0] += a.y*wb.x; hacc[ri][1] += a.y*wb.y;
                hacc[ri][2] += a.y*wb.z; hacc[ri][3] += a.y*wb.w;
            }
        }
        float bbv[4];
        #pragma unroll
        for(int j = 0; j < 4; j++) bbv[j] = bb[(l*3 + g)*HD + tc*4 + j];
        #pragma unroll
        for(int ri = 0; ri < 4; ri++)
            #pragma unroll
            for(int j = 0; j < 4; j++) hacc[ri][j] += bbv[j];
        __syncthreads();
    }

    #pragma unroll
    for(int ri = 0; ri < 4; ri++){
        int row = r0 + tr*4 + ri;
        float4* hp = (float4*)&g_h[row*HD + tc*4];
        float4 hv = *hp;
        hv.x += hacc[ri][0]; hv.y += hacc[ri][1];
        hv.z += hacc[ri][2]; hv.w += hacc[ri][3];
        *hp = hv;
    }
}

__global__ void k_readout(const float* __restrict__ ow1, const float* __restrict__ ob1,
                          const float* __restrict__ ow2, const float* __restrict__ ob2,
                          float* __restrict__ out){
    __shared__ float sS[NB*HD];
    __shared__ float sV[NB*32];
    int t = threadIdx.x;
    int b = t >> 6, f = t & 63;
    float s = 0.0f;
    const float* hp = g_h + (size_t)(b*ATN + M1N)*HD + f;
    #pragma unroll 4
    for(int i = 0; i < M2N; i++) s += hp[(size_t)i*HD];
    sS[b*HD + f] = s;
    __syncthreads();
    if(t < NB*32){
        int b2 = t >> 5, j = t & 31;
        float v = 0.0f;
        #pragma unroll 8
        for(int f2 = 0; f2 < HD; f2++) v += sS[b2*HD + f2] * ow1[f2*32 + j];
        sV[b2*32 + j] = v + (float)M2N * ob1[j];
    }
    __syncthreads();
    if(t < NB){
        float o = 0.0f;
        #pragma unroll
        for(int j = 0; j < 32; j++) o += sV[t*32 + j] * ow2[j];
        out[t] = o + (float)M2N * ob2[0];
    }
}

extern "C" void kernel_launch(void* const* d_in, const int* in_sizes, int n_in,
                              void* d_out, int out_size){
    (void)in_sizes; (void)n_in; (void)out_size;
    const int*   sites  = (const int*)d_in[0];
    const int*   sitesp = (const int*)d_in[1];
    const int*   ei1 = (const int*)d_in[2];
    const float* ew1 = (const float*)d_in[3];
    const int*   c1  = (const int*)d_in[4];
    const int*   ei2 = (const int*)d_in[5];
    const float* ew2 = (const float*)d_in[6];
    const int*   c2  = (const int*)d_in[7];
    const int*   ei3 = (const int*)d_in[8];
    const float* ew3 = (const float*)d_in[9];
    const int*   c3  = (const int*)d_in[10];
    const float* embw  = (const float*)d_in[11];
    const float* embpw = (const float*)d_in[12];
    const float* mw1 = (const float*)d_in[13];
    const float* mb1 = (const float*)d_in[14];
    const float* mw2 = (const float*)d_in[15];
    const float* mb2 = (const float*)d_in[16];
    const float* cw1 = (const float*)d_in[17];
    const float* cw2 = (const float*)d_in[18];
    const float* cb2 = (const float*)d_in[19];
    const float* bw  = (const float*)d_in[20];
    const float* bb  = (const float*)d_in[21];
    const float* ow1 = (const float*)d_in[22];
    const float* ob1 = (const float*)d_in[23];
    const float* ow2 = (const float*)d_in[24];
    const float* ob2 = (const float*)d_in[25];
    float* out = (float*)d_out;

    k_count<<<(ETN + 255)/256, 256>>>(ei1, ei2, ei3, ew1, ew2, ew3, c1, c2, c3); // 1
    k_cbase_rs<<<3, 32>>>();                                                     // 2
    k_fill<<<(ETN + 255)/256, 256>>>(ei1, ei2, ei3, ew1, ew2, ew3, c1, c2, c3);  // 3

    dim3 gw((E1N + 63)/64, CN, LN*3);
    k_wmlp<<<gw, 128>>>(mw1, mb1, mw2, mb2);                                     // 4 <- profiled
    k_embed<<<(NN*HD + 255)/256, 256>>>(sites, sitesp, embw, embpw);

    for(int l = 0; l < LN; l++){
        k_lin1<<<dim3(NN/64, 3), 128>>>(cw1, l);
        k_agg<<<dim3(ATN/8, 3), 256>>>(l);
        k_block<<<NN/32, 128>>>(cw2, cb2, bw, bb, l);
    }
    k_readout<<<1, 512>>>(ow1, ob1, ow2, ob2, out);
    k_cleanup<<<(3*ATN + 255)/256, 256>>>();
}

// round 15
// speedup vs baseline: 1.3687x; 1.0084x over previous
#include <cuda_runtime.h>
#include <math.h>

#define NB 8
#define M1N 2000
#define M2N 400
#define ATN 2400
#define NN (NB*ATN)
#define HD 64
#define NGN 50
#define NBUK 50
#define LN 4
#define CN 4
#define E1N 60000
#define E2N 20000
#define E3N 20000
#define ETN 100000

typedef unsigned long long u64;

__device__ float g_h[NN*HD];
__device__ float g_x[3][NN*HD];
__device__ float g_agg[3][NN*HD];
__device__ float g_W[LN*ETN*HD];
__device__ float g_d[ETN];
__device__ float g_ccut[ETN];
__device__ int   g_kq[ETN];
__device__ int2  g_csr[ETN];
__device__ int   g_cnt[3*ATN];        // zero-init; re-zeroed by k_cleanup
__device__ int   g_cur[3*ATN];
__device__ int   g_rs[3*(ATN+1)];
__device__ int   g_cc2[3*CN*NBUK];
__device__ int   g_ccur2[3*CN*NBUK];
__device__ int   g_cb2[3*CN*NBUK];

__device__ __forceinline__ float sspf(float x){
    return fmaxf(x, 0.0f) + log1pf(__expf(-fabsf(x))) - 0.6931471805599453f;
}

__device__ __forceinline__ void fma2(u64& d, u64 a, u64 b){
    asm("fma.rn.f32x2 %0, %1, %2, %0;" : "+l"(d) : "l"(a), "l"(b));
}

__device__ __forceinline__ int bucket_of(float d){
    int b = (int)(d * 4.9f);
    return min(NBUK-1, max(0, b));
}

__device__ __forceinline__ void resolve_edge(int idx, int& g, int& e, int& eofs){
    if(idx < E1N){ g = 0; e = idx; eofs = 0; }
    else if(idx < E1N+E2N){ g = 1; e = idx-E1N; eofs = E1N; }
    else { g = 2; e = idx-E1N-E2N; eofs = E1N+E2N; }
}

// ---------------- preprocessing ----------------
__global__ void k_count(const int* __restrict__ e1, const int* __restrict__ e2,
                        const int* __restrict__ e3,
                        const float* __restrict__ w1, const float* __restrict__ w2,
                        const float* __restrict__ w3,
                        const int* __restrict__ c1, const int* __restrict__ c2,
                        const int* __restrict__ c3){
    int idx = blockIdx.x*blockDim.x + threadIdx.x;
    if(idx >= ETN) return;
    int g, e, eofs; resolve_edge(idx, g, e, eofs);
    const int* cp  = (g==0) ? c1 : ((g==1) ? c2 : c3);
    const int* eip = (g==0) ? e1 : ((g==1) ? e2 : e3);
    const float* wp = (g==0) ? w1 : ((g==1) ? w2 : w3);
    int b = bucket_of(wp[e]);
    atomicAdd(&g_cc2[(g*CN + cp[e])*NBUK + b], 1);
    atomicAdd(&g_cnt[g*ATN + eip[2*e + 1]], 1);
}

__global__ void k_cbase_rs(){
    int g = blockIdx.x;
    int lane = threadIdx.x;
    {
        const int per = ATN / 32;
        int base = lane * per;
        int sum = 0;
        for(int i = 0; i < per; i++) sum += g_cnt[g*ATN + base + i];
        int incl = sum;
        #pragma unroll
        for(int o = 1; o < 32; o <<= 1){
            int v = __shfl_up_sync(0xFFFFFFFFu, incl, o);
            if(lane >= o) incl += v;
        }
        int run = incl - sum;
        for(int i = 0; i < per; i++){
            g_rs[g*(ATN+1) + base + i] = run;
            run += g_cnt[g*ATN + base + i];
        }
        if(lane == 31) g_rs[g*(ATN+1) + ATN] = run;
    }
    {
        const int M = CN*NBUK;
        const int per = (M + 31) / 32;
        int base = lane * per;
        int sum = 0;
        for(int i = 0; i < per; i++){
            int id = base + i;
            if(id < M) sum += g_cc2[g*M + id];
        }
        int incl = sum;
        #pragma unroll
        for(int o = 1; o < 32; o <<= 1){
            int v = __shfl_up_sync(0xFFFFFFFFu, incl, o);
            if(lane >= o) incl += v;
        }
        int run = incl - sum;
        for(int i = 0; i < per; i++){
            int id = base + i;
            if(id < M){ g_cb2[g*M + id] = run; run += g_cc2[g*M + id]; }
        }
    }
}

__global__ void k_fill(const int* __restrict__ e1, const int* __restrict__ e2,
                       const int* __restrict__ e3,
                       const float* __restrict__ w1, const float* __restrict__ w2,
                       const float* __restrict__ w3,
                       const int* __restrict__ c1, const int* __restrict__ c2,
                       const int* __restrict__ c3){
    int idx = blockIdx.x*blockDim.x + threadIdx.x;
    if(idx >= ETN) return;
    int g, e, eofs; resolve_edge(idx, g, e, eofs);
    const int* cp  = (g==0) ? c1 : ((g==1) ? c2 : c3);
    const int* eip = (g==0) ? e1 : ((g==1) ? e2 : e3);
    const float* wp = (g==0) ? w1 : ((g==1) ? w2 : w3);
    int col = cp[e];
    float d = wp[e];
    int b = bucket_of(d);
    int slot = (g*CN + col)*NBUK + b;
    int p = g_cb2[slot] + atomicAdd(&g_ccur2[slot], 1);
    g_kq[eofs + p] = b;
    g_d[eofs + p] = d;
    g_ccut[eofs + p] = 0.5f * (cosf(d * 3.14159265358979323846f / 10.0f) + 1.0f);
    int src = eip[2*e], dst = eip[2*e + 1];
    int pc = g_rs[g*(ATN+1) + dst] + atomicAdd(&g_cur[g*ATN + dst], 1);
    g_csr[eofs + pc] = make_int2(src, p);
}

__global__ void k_embed(const int* __restrict__ sites, const int* __restrict__ sitesp,
                        const float* __restrict__ embw, const float* __restrict__ embpw){
    int idx = blockIdx.x*blockDim.x + threadIdx.x;
    if(idx >= NN*HD) return;
    int n = idx >> 6, f = idx & 63;
    int b = n / ATN, i = n - b*ATN;
    float v;
    if(i < M1N) v = embw[sites[b*M1N + i]*HD + f];
    else        v = embpw[sitesp[b*M2N + (i - M1N)]*HD + f];
    g_h[idx] = v;
}

__global__ void k_cleanup(){
    int i = blockIdx.x*blockDim.x + threadIdx.x;
    if(i < 3*ATN){ g_cnt[i] = 0; g_cur[i] = 0; }
    if(i < 3*CN*NBUK){ g_cc2[i] = 0; g_ccur2[i] = 0; }
}

// ---------------- edge-filter MLP: one launch (z = l*3+g), 32-row weight halves ----
__global__ void __launch_bounds__(128, 8)
k_wmlp(const float* __restrict__ mw1, const float* __restrict__ mb1,
       const float* __restrict__ mw2, const float* __restrict__ mb2){
    const int c = blockIdx.y;
    const int lz = blockIdx.z;
    const int l = lz / 3, g = lz - l*3;
    const int eofs = (g == 0) ? 0 : ((g == 1) ? E1N : (E1N + E2N));
    const int etot = (g == 0) ? E1N : ((g == 1) ? E2N : E3N);
    const int cb = g_cb2[(g*CN + c)*NBUK];
    const int ce = (c == CN-1) ? etot : g_cb2[(g*CN + c + 1)*NBUK];
    const int r0 = cb + blockIdx.x*64;
    if(r0 >= ce) return;
    const int t = threadIdx.x;
    const int tc = t & 15, tr = t >> 4;

    __shared__ __align__(16) float sW[32*64];   // 32-row weight half-tile (8KB)
    __shared__ __align__(16) float sU[64*66];   // attr window, then H tile

    const int b0 = g_kq[eofs + r0];
    const int b1 = g_kq[eofs + min(r0 + 63, ce - 1)];
    const int k0 = max(0, b0 - 6);
    const int kend = min(NGN - 1, b1 + 7);
    const int Wd = kend - k0 + 1;

    const int pgc = (l*3 + g)*CN + c;
    const float* w1 = mw1 + pgc*NGN*HD;
    {
        const float step = 10.0f / 49.0f;
        const float coeff = -0.5f / (step*step);
        int total = 64 * Wd;
        for(int i = t; i < total; i += 128){
            int rr = i / Wd;
            int kk = k0 + (i - rr*Wd);
            int row = r0 + rr;
            float v = 0.0f;
            if(row < ce){
                float d = __ldg(&g_d[eofs + row]);
                float tt = d - step * (float)kk;
                v = __expf(coeff * tt * tt);
            }
            sU[rr*66 + kk] = v;
        }
    }

    float acc[8][4];
    #pragma unroll
    for(int ri = 0; ri < 8; ri++){ acc[ri][0]=0; acc[ri][1]=0; acc[ri][2]=0; acc[ri][3]=0; }
    for(int kb = k0; kb <= kend; kb += 32){
        int kh = min(kend, kb + 31);
        int nrows = kh - kb + 1;
        for(int i = t; i < nrows*HD; i += 128) sW[i] = w1[kb*HD + i];
        __syncthreads();
        for(int k = kb; k <= kh; k++){
            float4 w = *(const float4*)&sW[(k-kb)*64 + tc*4];
            #pragma unroll
            for(int ri = 0; ri < 8; ri++){
                float a = sU[(tr*8 + ri)*66 + k];
                acc[ri][0] += a*w.x; acc[ri][1] += a*w.y;
                acc[ri][2] += a*w.z; acc[ri][3] += a*w.w;
            }
        }
        __syncthreads();
    }

    float b1v[4];
    #pragma unroll
    for(int j = 0; j < 4; j++) b1v[j] = mb1[pgc*HD + tc*4 + j];
    #pragma unroll
    for(int ri = 0; ri < 8; ri++)
        #pragma unroll
        for(int j = 0; j < 4; j++)
            sU[(tr*8 + ri)*66 + tc*4 + j] = sspf(acc[ri][j] + b1v[j]);

    const float* w2 = mw2 + pgc*HD*HD;
    float acc2[8][4];
    #pragma unroll
    for(int ri = 0; ri < 8; ri++){ acc2[ri][0]=0; acc2[ri][1]=0; acc2[ri][2]=0; acc2[ri][3]=0; }
    for(int kb2 = 0; kb2 < HD; kb2 += 32){
        for(int i = t; i < 32*HD; i += 128) sW[i] = w2[kb2*HD + i];
        __syncthreads();
        #pragma unroll 4
        for(int kk = 0; kk < 32; kk += 2){
            float4 wa = *(const float4*)&sW[kk*64 + tc*4];
            float4 wb = *(const float4*)&sW[(kk+1)*64 + tc*4];
            #pragma unroll
            for(int ri = 0; ri < 8; ri++){
                float2 a = *(const float2*)&sU[(tr*8 + ri)*66 + kb2 + kk];
                acc2[ri][0] += a.x*wa.x; acc2[ri][1] += a.x*wa.y;
                acc2[ri][2] += a.x*wa.z; acc2[ri][3] += a.x*wa.w;
                acc2[ri][0] += a.y*wb.x; acc2[ri][1] += a.y*wb.y;
                acc2[ri][2] += a.y*wb.z; acc2[ri][3] += a.y*wb.w;
            }
        }
        __syncthreads();
    }
    float b2v[4];
    #pragma unroll
    for(int j = 0; j < 4; j++) b2v[j] = mb2[pgc*HD + tc*4 + j];
    #pragma unroll
    for(int ri = 0; ri < 8; ri++){
        int row = r0 + tr*8 + ri;
        if(row < ce){
            float cc = g_ccut[eofs + row];
            float4 o;
            o.x = (acc2[ri][0] + b2v[0]) * cc;
            o.y = (acc2[ri][1] + b2v[1]) * cc;
            o.z = (acc2[ri][2] + b2v[2]) * cc;
            o.w = (acc2[ri][3] + b2v[3]) * cc;
            *(float4*)&g_W[(size_t)(l*ETN + eofs + row)*HD + tc*4] = o;
        }
    }
}

// ---------------- lin1 (layer 0 only) ----------------
__global__ void k_lin1(const float* __restrict__ cw1, int l){
    const int gph = blockIdx.y;
    const int r0 = blockIdx.x * 64;
    const int t = threadIdx.x, tc = t & 15, tr = t >> 4;
    __shared__ __align__(16) float sW[64*64];
    __shared__ __align__(16) float sHt[64*66];
    const float* w = cw1 + (l*3 + gph)*HD*HD;
    for(int i = t; i < HD*HD; i += 128) sW[i] = w[i];
    for(int i = t; i < 64*64; i += 128){
        int rr = i >> 6, kk = i & 63;
        sHt[rr*66 + kk] = g_h[(r0 + rr)*HD + kk];
    }
    __syncthreads();
    float acc[8][4];
    #pragma unroll
    for(int ri = 0; ri < 8; ri++){ acc[ri][0]=0; acc[ri][1]=0; acc[ri][2]=0; acc[ri][3]=0; }
    for(int k = 0; k < HD; k += 2){
        float4 wa = *(const float4*)&sW[k*64 + tc*4];
        float4 wb = *(const float4*)&sW[(k+1)*64 + tc*4];
        #pragma unroll
        for(int ri = 0; ri < 8; ri++){
            float2 a = *(const float2*)&sHt[(tr*8 + ri)*66 + k];
            acc[ri][0] += a.x*wa.x; acc[ri][1] += a.x*wa.y;
            acc[ri][2] += a.x*wa.z; acc[ri][3] += a.x*wa.w;
            acc[ri][0] += a.y*wb.x; acc[ri][1] += a.y*wb.y;
            acc[ri][2] += a.y*wb.z; acc[ri][3] += a.y*wb.w;
        }
    }
    float* xo = g_x[gph];
    #pragma unroll
    for(int ri = 0; ri < 8; ri++){
        int row = r0 + tr*8 + ri;
        float4 o; o.x = acc[ri][0]; o.y = acc[ri][1]; o.z = acc[ri][2]; o.w = acc[ri][3];
        *(float4*)&xo[row*HD + tc*4] = o;
    }
}

// ---------------- CSR aggregation: int2 index stream + 2-edge unroll ----------------
__global__ void k_agg(int l){
    const int gph = blockIdx.y;
    const int t = threadIdx.x;
    const int f2 = t & 31;
    const int dq = t >> 5;
    const int dst = blockIdx.x*8 + dq;
    const int eofs = (gph == 0) ? 0 : ((gph == 1) ? E1N : (E1N + E2N));
    const int s = g_rs[gph*(ATN+1) + dst];
    const int e = g_rs[gph*(ATN+1) + dst + 1];
    const u64* __restrict__ xq = (const u64*)g_x[gph];
    const u64* __restrict__ Wq = (const u64*)(g_W + (size_t)l*ETN*HD) + (size_t)eofs*32;
    u64 acc[NB];
    #pragma unroll
    for(int b = 0; b < NB; b++) acc[b] = 0ull;
    int p = s;
    for(; p + 1 < e; p += 2){
        int2 c0 = __ldg(&g_csr[eofs + p]);
        int2 c1 = __ldg(&g_csr[eofs + p + 1]);
        u64 w0 = Wq[(size_t)c0.y*32 + f2];
        u64 w1 = Wq[(size_t)c1.y*32 + f2];
        int base0 = c0.x*32 + f2;
        int base1 = c1.x*32 + f2;
        #pragma unroll
        for(int b = 0; b < NB; b++){
            fma2(acc[b], xq[base0 + b*ATN*32], w0);
            fma2(acc[b], xq[base1 + b*ATN*32], w1);
        }
    }
    if(p < e){
        int2 c0 = __ldg(&g_csr[eofs + p]);
        u64 w0 = Wq[(size_t)c0.y*32 + f2];
        int base0 = c0.x*32 + f2;
        #pragma unroll
        for(int b = 0; b < NB; b++)
            fma2(acc[b], xq[base0 + b*ATN*32], w0);
    }
    u64* aq = (u64*)g_agg[gph];
    int ob = dst*32 + f2;
    #pragma unroll
    for(int b = 0; b < NB; b++)
        aq[ob + b*ATN*32] = acc[b];
}

// ---------------- block (32-row) + fused next-layer lin1 ----------------
__global__ void k_block(const float* __restrict__ cw2, const float* __restrict__ cb2,
                        const float* __restrict__ bw, const float* __restrict__ bb,
                        const float* __restrict__ cw1, int l, int next){
    const int r0 = blockIdx.x * 32;
    const int t = threadIdx.x, tc = t & 15, tr = t >> 4;
    __shared__ __align__(16) float sW[64*64];
    __shared__ __align__(16) float sAg[32*66];
    __shared__ __align__(16) float sT[32*66];
    float hacc[4][4];
    #pragma unroll
    for(int ri = 0; ri < 4; ri++){ hacc[ri][0]=0; hacc[ri][1]=0; hacc[ri][2]=0; hacc[ri][3]=0; }

    for(int g = 0; g < 3; g++){
        const float* w = cw2 + (l*3 + g)*HD*HD;
        for(int i = t; i < HD*HD; i += 128) sW[i] = w[i];
        const float* ag = g_agg[g];
        for(int i = t; i < 32*64; i += 128){
            int rr = i >> 6, kk = i & 63;
            sAg[rr*66 + kk] = ag[(r0 + rr)*HD + kk];
        }
        __syncthreads();

        float acc[4][4];
        #pragma unroll
        for(int ri = 0; ri < 4; ri++){ acc[ri][0]=0; acc[ri][1]=0; acc[ri][2]=0; acc[ri][3]=0; }
        for(int k = 0; k < HD; k += 2){
            float4 wa = *(const float4*)&sW[k*64 + tc*4];
            float4 wb = *(const float4*)&sW[(k+1)*64 + tc*4];
            #pragma unroll
            for(int ri = 0; ri < 4; ri++){
                float2 a = *(const float2*)&sAg[(tr*4 + ri)*66 + k];
                acc[ri][0] += a.x*wa.x; acc[ri][1] += a.x*wa.y;
                acc[ri][2] += a.x*wa.z; acc[ri][3] += a.x*wa.w;
                acc[ri][0] += a.y*wb.x; acc[ri][1] += a.y*wb.y;
                acc[ri][2] += a.y*wb.z; acc[ri][3] += a.y*wb.w;
            }
        }
        float b2v[4];
        #pragma unroll
        for(int j = 0; j < 4; j++) b2v[j] = cb2[(l*3 + g)*HD + tc*4 + j];
        #pragma unroll
        for(int ri = 0; ri < 4; ri++)
            #pragma unroll
            for(int j = 0; j < 4; j++)
                sT[(tr*4 + ri)*66 + tc*4 + j] = sspf(acc[ri][j] + b2v[j]);
        __syncthreads();

        const float* w2 = bw + (l*3 + g)*HD*HD;
        for(int i = t; i < HD*HD; i += 128) sW[i] = w2[i];
        __syncthreads();

        for(int k = 0; k < HD; k += 2){
            float4 wa = *(const float4*)&sW[k*64 + tc*4];
            float4 wb = *(const float4*)&sW[(k+1)*64 + tc*4];
            #pragma unroll
            for(int ri = 0; ri < 4; ri++){
                float2 a = *(const float2*)&sT[(tr*4 + ri)*66 + k];
                hacc[ri][0] += a.x*wa.x; hacc[ri][1] += a.x*wa.y;
                hacc[ri][2] += a.x*wa.z; hacc[ri][3] += a.x*wa.w;
                hacc[ri][0] += a.y*wb.x; hacc[ri][1] += a.y*wb.y;
                hacc[ri][2] += a.y*wb.z; hacc[ri][3] += a.y*wb.w;
            }
        }
        float bbv[4];
        #pragma unroll
        for(int j = 0; j < 4; j++) bbv[j] = bb[(l*3 + g)*HD + tc*4 + j];
        #pragma unroll
        for(int ri = 0; ri < 4; ri++)
            #pragma unroll
            for(int j = 0; j < 4; j++) hacc[ri][j] += bbv[j];
        __syncthreads();
    }

    // h += delta; stash updated h rows in sAg for the fused lin1
    #pragma unroll
    for(int ri = 0; ri < 4; ri++){
        int row = r0 + tr*4 + ri;
        float4* hp = (float4*)&g_h[row*HD + tc*4];
        float4 hv = *hp;
        hv.x += hacc[ri][0]; hv.y += hacc[ri][1];
        hv.z += hacc[ri][2]; hv.w += hacc[ri][3];
        *hp = hv;
        float* sr = &sAg[(tr*4 + ri)*66 + tc*4];
        sr[0] = hv.x; sr[1] = hv.y; sr[2] = hv.z; sr[3] = hv.w;
    }

    if(next){
        for(int g = 0; g < 3; g++){
            const float* w = cw1 + ((l+1)*3 + g)*HD*HD;
            for(int i = t; i < HD*HD; i += 128) sW[i] = w[i];
            __syncthreads();   // covers sAg stores on first iteration
            float acc[4][4];
            #pragma unroll
            for(int ri = 0; ri < 4; ri++){ acc[ri][0]=0; acc[ri][1]=0; acc[ri][2]=0; acc[ri][3]=0; }
            for(int k = 0; k < HD; k += 2){
                float4 wa = *(const float4*)&sW[k*64 + tc*4];
                float4 wb = *(const float4*)&sW[(k+1)*64 + tc*4];
                #pragma unroll
                for(int ri = 0; ri < 4; ri++){
                    float2 a = *(const float2*)&sAg[(tr*4 + ri)*66 + k];
                    acc[ri][0] += a.x*wa.x; acc[ri][1] += a.x*wa.y;
                    acc[ri][2] += a.x*wa.z; acc[ri][3] += a.x*wa.w;
                    acc[ri][0] += a.y*wb.x; acc[ri][1] += a.y*wb.y;
                    acc[ri][2] += a.y*wb.z; acc[ri][3] += a.y*wb.w;
                }
            }
            float* xo = g_x[g];
            #pragma unroll
            for(int ri = 0; ri < 4; ri++){
                int row = r0 + tr*4 + ri;
                float4 o; o.x = acc[ri][0]; o.y = acc[ri][1]; o.z = acc[ri][2]; o.w = acc[ri][3];
                *(float4*)&xo[row*HD + tc*4] = o;
            }
            __syncthreads();   // before next g overwrites sW
        }
    }
}

__global__ void k_readout(const float* __restrict__ ow1, const float* __restrict__ ob1,
                          const float* __restrict__ ow2, const float* __restrict__ ob2,
                          float* __restrict__ out){
    __shared__ float sS[NB*HD];
    __shared__ float sV[NB*32];
    int t = threadIdx.x;
    int b = t >> 6, f = t & 63;
    float s = 0.0f;
    const float* hp = g_h + (size_t)(b*ATN + M1N)*HD + f;
    #pragma unroll 4
    for(int i = 0; i < M2N; i++) s += hp[(size_t)i*HD];
    sS[b*HD + f] = s;
    __syncthreads();
    if(t < NB*32){
        int b2 = t >> 5, j = t & 31;
        float v = 0.0f;
        #pragma unroll 8
        for(int f2 = 0; f2 < HD; f2++) v += sS[b2*HD + f2] * ow1[f2*32 + j];
        sV[b2*32 + j] = v + (float)M2N * ob1[j];
    }
    __syncthreads();
    if(t < NB){
        float o = 0.0f;
        #pragma unroll
        for(int j = 0; j < 32; j++) o += sV[t*32 + j] * ow2[j];
        out[t] = o + (float)M2N * ob2[0];
    }
}

extern "C" void kernel_launch(void* const* d_in, const int* in_sizes, int n_in,
                              void* d_out, int out_size){
    (void)in_sizes; (void)n_in; (void)out_size;
    const int*   sites  = (const int*)d_in[0];
    const int*   sitesp = (const int*)d_in[1];
    const int*   ei1 = (const int*)d_in[2];
    const float* ew1 = (const float*)d_in[3];
    const int*   c1  = (const int*)d_in[4];
    const int*   ei2 = (const int*)d_in[5];
    const float* ew2 = (const float*)d_in[6];
    const int*   c2  = (const int*)d_in[7];
    const int*   ei3 = (const int*)d_in[8];
    const float* ew3 = (const float*)d_in[9];
    const int*   c3  = (const int*)d_in[10];
    const float* embw  = (const float*)d_in[11];
    const float* embpw = (const float*)d_in[12];
    const float* mw1 = (const float*)d_in[13];
    const float* mb1 = (const float*)d_in[14];
    const float* mw2 = (const float*)d_in[15];
    const float* mb2 = (const float*)d_in[16];
    const float* cw1 = (const float*)d_in[17];
    const float* cw2 = (const float*)d_in[18];
    const float* cb2 = (const float*)d_in[19];
    const float* bw  = (const float*)d_in[20];
    const float* bb  = (const float*)d_in[21];
    const float* ow1 = (const float*)d_in[22];
    const float* ob1 = (const float*)d_in[23];
    const float* ow2 = (const float*)d_in[24];
    const float* ob2 = (const float*)d_in[25];
    float* out = (float*)d_out;

    k_count<<<(ETN + 255)/256, 256>>>(ei1, ei2, ei3, ew1, ew2, ew3, c1, c2, c3); // 1
    k_cbase_rs<<<3, 32>>>();                                                     // 2
    k_fill<<<(ETN + 255)/256, 256>>>(ei1, ei2, ei3, ew1, ew2, ew3, c1, c2, c3);  // 3

    dim3 gw((E1N + 63)/64, CN, LN*3);
    k_wmlp<<<gw, 128>>>(mw1, mb1, mw2, mb2);                                     // 4 <- profiled
    k_embed<<<(NN*HD + 255)/256, 256>>>(sites, sitesp, embw, embpw);
    k_lin1<<<dim3(NN/64, 3), 128>>>(cw1, 0);

    for(int l = 0; l < LN; l++){
        k_agg<<<dim3(ATN/8, 3), 256>>>(l);
        k_block<<<NN/32, 128>>>(cw2, cb2, bw, bb, cw1, l, (l + 1 < LN) ? 1 : 0);
    }
    k_readout<<<1, 512>>>(ow1, ob1, ow2, ob2, out);
    k_cleanup<<<(3*ATN + 255)/256, 256>>>();
}

// round 16
// speedup vs baseline: 1.4464x; 1.0568x over previous
#include <cuda_runtime.h>
#include <math.h>

#define NB 8
#define M1N 2000
#define M2N 400
#define ATN 2400
#define NN (NB*ATN)
#define HD 64
#define NGN 50
#define NBUK 50
#define LN 4
#define CN 4
#define E1N 60000
#define E2N 20000
#define E3N 20000
#define ETN 100000

typedef unsigned long long u64;

__device__ float g_h[NN*HD];
__device__ float g_x[3][NN*HD];
__device__ float g_agg[3][NN*HD];
__device__ float g_W[LN*ETN*HD];
__device__ float g_d[ETN];
__device__ float g_ccut[ETN];
__device__ int   g_kq[ETN];
__device__ int2  g_csr[ETN];
__device__ int   g_cnt[3*ATN];        // zero-init; re-zeroed by k_cleanup
__device__ int   g_cur[3*ATN];
__device__ int   g_rs[3*(ATN+1)];
__device__ int   g_cc2[3*CN*NBUK];
__device__ int   g_ccur2[3*CN*NBUK];
__device__ int   g_cb2[3*CN*NBUK];

// fast shifted-softplus: max(x,0) + log(1+exp(-|x|)) - log2
// __logf on [1,2] has ~1e-7 abs err; well inside the 1e-3 test tolerance.
__device__ __forceinline__ float sspf(float x){
    return fmaxf(x, 0.0f) + __logf(1.0f + __expf(-fabsf(x))) - 0.6931471805599453f;
}

__device__ __forceinline__ void fma2(u64& d, u64 a, u64 b){
    asm("fma.rn.f32x2 %0, %1, %2, %0;" : "+l"(d) : "l"(a), "l"(b));
}

__device__ __forceinline__ int bucket_of(float d){
    int b = (int)(d * 4.9f);
    return min(NBUK-1, max(0, b));
}

__device__ __forceinline__ void resolve_edge(int idx, int& g, int& e, int& eofs){
    if(idx < E1N){ g = 0; e = idx; eofs = 0; }
    else if(idx < E1N+E2N){ g = 1; e = idx-E1N; eofs = E1N; }
    else { g = 2; e = idx-E1N-E2N; eofs = E1N+E2N; }
}

// ---------------- preprocessing ----------------
__global__ void k_count(const int* __restrict__ e1, const int* __restrict__ e2,
                        const int* __restrict__ e3,
                        const float* __restrict__ w1, const float* __restrict__ w2,
                        const float* __restrict__ w3,
                        const int* __restrict__ c1, const int* __restrict__ c2,
                        const int* __restrict__ c3){
    int idx = blockIdx.x*blockDim.x + threadIdx.x;
    if(idx >= ETN) return;
    int g, e, eofs; resolve_edge(idx, g, e, eofs);
    const int* cp  = (g==0) ? c1 : ((g==1) ? c2 : c3);
    const int* eip = (g==0) ? e1 : ((g==1) ? e2 : e3);
    const float* wp = (g==0) ? w1 : ((g==1) ? w2 : w3);
    int b = bucket_of(wp[e]);
    atomicAdd(&g_cc2[(g*CN + cp[e])*NBUK + b], 1);
    atomicAdd(&g_cnt[g*ATN + eip[2*e + 1]], 1);
}

__global__ void k_cbase_rs(){
    int g = blockIdx.x;
    int lane = threadIdx.x;
    {
        const int per = ATN / 32;
        int base = lane * per;
        int sum = 0;
        for(int i = 0; i < per; i++) sum += g_cnt[g*ATN + base + i];
        int incl = sum;
        #pragma unroll
        for(int o = 1; o < 32; o <<= 1){
            int v = __shfl_up_sync(0xFFFFFFFFu, incl, o);
            if(lane >= o) incl += v;
        }
        int run = incl - sum;
        for(int i = 0; i < per; i++){
            g_rs[g*(ATN+1) + base + i] = run;
            run += g_cnt[g*ATN + base + i];
        }
        if(lane == 31) g_rs[g*(ATN+1) + ATN] = run;
    }
    {
        const int M = CN*NBUK;
        const int per = (M + 31) / 32;
        int base = lane * per;
        int sum = 0;
        for(int i = 0; i < per; i++){
            int id = base + i;
            if(id < M) sum += g_cc2[g*M + id];
        }
        int incl = sum;
        #pragma unroll
        for(int o = 1; o < 32; o <<= 1){
            int v = __shfl_up_sync(0xFFFFFFFFu, incl, o);
            if(lane >= o) incl += v;
        }
        int run = incl - sum;
        for(int i = 0; i < per; i++){
            int id = base + i;
            if(id < M){ g_cb2[g*M + id] = run; run += g_cc2[g*M + id]; }
        }
    }
}

__global__ void k_fill(const int* __restrict__ e1, const int* __restrict__ e2,
                       const int* __restrict__ e3,
                       const float* __restrict__ w1, const float* __restrict__ w2,
                       const float* __restrict__ w3,
                       const int* __restrict__ c1, const int* __restrict__ c2,
                       const int* __restrict__ c3){
    int idx = blockIdx.x*blockDim.x + threadIdx.x;
    if(idx >= ETN) return;
    int g, e, eofs; resolve_edge(idx, g, e, eofs);
    const int* cp  = (g==0) ? c1 : ((g==1) ? c2 : c3);
    const int* eip = (g==0) ? e1 : ((g==1) ? e2 : e3);
    const float* wp = (g==0) ? w1 : ((g==1) ? w2 : w3);
    int col = cp[e];
    float d = wp[e];
    int b = bucket_of(d);
    int slot = (g*CN + col)*NBUK + b;
    int p = g_cb2[slot] + atomicAdd(&g_ccur2[slot], 1);
    g_kq[eofs + p] = b;
    g_d[eofs + p] = d;
    g_ccut[eofs + p] = 0.5f * (cosf(d * 3.14159265358979323846f / 10.0f) + 1.0f);
    int src = eip[2*e], dst = eip[2*e + 1];
    int pc = g_rs[g*(ATN+1) + dst] + atomicAdd(&g_cur[g*ATN + dst], 1);
    g_csr[eofs + pc] = make_int2(src, p);
}

__global__ void k_embed(const int* __restrict__ sites, const int* __restrict__ sitesp,
                        const float* __restrict__ embw, const float* __restrict__ embpw){
    int idx = blockIdx.x*blockDim.x + threadIdx.x;
    if(idx >= NN*HD) return;
    int n = idx >> 6, f = idx & 63;
    int b = n / ATN, i = n - b*ATN;
    float v;
    if(i < M1N) v = embw[sites[b*M1N + i]*HD + f];
    else        v = embpw[sitesp[b*M2N + (i - M1N)]*HD + f];
    g_h[idx] = v;
}

__global__ void k_cleanup(){
    int i = blockIdx.x*blockDim.x + threadIdx.x;
    if(i < 3*ATN){ g_cnt[i] = 0; g_cur[i] = 0; }
    if(i < 3*CN*NBUK){ g_cc2[i] = 0; g_ccur2[i] = 0; }
}

// ---------------- edge-filter MLP: one launch (z = l*3+g), 32-row weight halves ----
__global__ void k_wmlp(const float* __restrict__ mw1, const float* __restrict__ mb1,
                       const float* __restrict__ mw2, const float* __restrict__ mb2){
    const int c = blockIdx.y;
    const int lz = blockIdx.z;
    const int l = lz / 3, g = lz - l*3;
    const int eofs = (g == 0) ? 0 : ((g == 1) ? E1N : (E1N + E2N));
    const int etot = (g == 0) ? E1N : ((g == 1) ? E2N : E3N);
    const int cb = g_cb2[(g*CN + c)*NBUK];
    const int ce = (c == CN-1) ? etot : g_cb2[(g*CN + c + 1)*NBUK];
    const int r0 = cb + blockIdx.x*64;
    if(r0 >= ce) return;
    const int t = threadIdx.x;
    const int tc = t & 15, tr = t >> 4;

    __shared__ __align__(16) float sW[32*64];   // 32-row weight half-tile (8KB)
    __shared__ __align__(16) float sU[64*66];   // attr window, then H tile

    const int b0 = g_kq[eofs + r0];
    const int b1 = g_kq[eofs + min(r0 + 63, ce - 1)];
    const int k0 = max(0, b0 - 6);
    const int kend = min(NGN - 1, b1 + 7);

    const int pgc = (l*3 + g)*CN + c;
    const float* w1 = mw1 + pgc*NGN*HD;
    // division-free attr fill: row = t&63, half = t>>6; one d load per thread
    {
        const float step = 10.0f / 49.0f;
        const float coeff = -0.5f / (step*step);
        int rr = t & 63;
        int half = t >> 6;                   // 0 or 1
        int row = r0 + rr;
        float d = (row < ce) ? __ldg(&g_d[eofs + row]) : 1e30f;
        int Wd = kend - k0 + 1;
        int hw = (Wd + 1) >> 1;
        int ks = k0 + half*hw;
        int ke = min(kend, ks + hw - 1);
        float* su = &sU[rr*66];
        for(int kk = ks; kk <= ke; kk++){
            float tt = d - step * (float)kk;
            float v = __expf(coeff * tt * tt);
            su[kk] = (row < ce) ? v : 0.0f;
        }
    }

    float acc[8][4];
    #pragma unroll
    for(int ri = 0; ri < 8; ri++){ acc[ri][0]=0; acc[ri][1]=0; acc[ri][2]=0; acc[ri][3]=0; }
    for(int kb = k0; kb <= kend; kb += 32){
        int kh = min(kend, kb + 31);
        int nrows = kh - kb + 1;
        for(int i = t; i < nrows*HD; i += 128) sW[i] = w1[kb*HD + i];
        __syncthreads();
        const float* wrow = &sW[tc*4];
        const float* arow = &sU[tr*8*66 + kb];
        int nk = kh - kb + 1;
        for(int k = 0; k < nk; k++){
            float4 w = *(const float4*)(wrow + k*64);
            #pragma unroll
            for(int ri = 0; ri < 8; ri++){
                float a = arow[ri*66 + k];
                acc[ri][0] += a*w.x; acc[ri][1] += a*w.y;
                acc[ri][2] += a*w.z; acc[ri][3] += a*w.w;
            }
        }
        __syncthreads();
    }

    float b1v[4];
    #pragma unroll
    for(int j = 0; j < 4; j++) b1v[j] = mb1[pgc*HD + tc*4 + j];
    #pragma unroll
    for(int ri = 0; ri < 8; ri++)
        #pragma unroll
        for(int j = 0; j < 4; j++)
            sU[(tr*8 + ri)*66 + tc*4 + j] = sspf(acc[ri][j] + b1v[j]);

    const float* w2 = mw2 + pgc*HD*HD;
    float acc2[8][4];
    #pragma unroll
    for(int ri = 0; ri < 8; ri++){ acc2[ri][0]=0; acc2[ri][1]=0; acc2[ri][2]=0; acc2[ri][3]=0; }
    for(int kb2 = 0; kb2 < HD; kb2 += 32){
        for(int i = t; i < 32*HD; i += 128) sW[i] = w2[kb2*HD + i];
        __syncthreads();
        #pragma unroll 4
        for(int kk = 0; kk < 32; kk += 2){
            float4 wa = *(const float4*)&sW[kk*64 + tc*4];
            float4 wb = *(const float4*)&sW[(kk+1)*64 + tc*4];
            #pragma unroll
            for(int ri = 0; ri < 8; ri++){
                float2 a = *(const float2*)&sU[(tr*8 + ri)*66 + kb2 + kk];
                acc2[ri][0] += a.x*wa.x; acc2[ri][1] += a.x*wa.y;
                acc2[ri][2] += a.x*wa.z; acc2[ri][3] += a.x*wa.w;
                acc2[ri][0] += a.y*wb.x; acc2[ri][1] += a.y*wb.y;
                acc2[ri][2] += a.y*wb.z; acc2[ri][3] += a.y*wb.w;
            }
        }
        __syncthreads();
    }
    float b2v[4];
    #pragma unroll
    for(int j = 0; j < 4; j++) b2v[j] = mb2[pgc*HD + tc*4 + j];
    #pragma unroll
    for(int ri = 0; ri < 8; ri++){
        int row = r0 + tr*8 + ri;
        if(row < ce){
            float cc = g_ccut[eofs + row];
            float4 o;
            o.x = (acc2[ri][0] + b2v[0]) * cc;
            o.y = (acc2[ri][1] + b2v[1]) * cc;
            o.z = (acc2[ri][2] + b2v[2]) * cc;
            o.w = (acc2[ri][3] + b2v[3]) * cc;
            *(float4*)&g_W[(size_t)(l*ETN + eofs + row)*HD + tc*4] = o;
        }
    }
}

// ---------------- lin1 (layer 0 only) ----------------
__global__ void k_lin1(const float* __restrict__ cw1, int l){
    const int gph = blockIdx.y;
    const int r0 = blockIdx.x * 64;
    const int t = threadIdx.x, tc = t & 15, tr = t >> 4;
    __shared__ __align__(16) float sW[64*64];
    __shared__ __align__(16) float sHt[64*66];
    const float* w = cw1 + (l*3 + gph)*HD*HD;
    for(int i = t; i < HD*HD; i += 128) sW[i] = w[i];
    for(int i = t; i < 64*64; i += 128){
        int rr = i >> 6, kk = i & 63;
        sHt[rr*66 + kk] = g_h[(r0 + rr)*HD + kk];
    }
    __syncthreads();
    float acc[8][4];
    #pragma unroll
    for(int ri = 0; ri < 8; ri++){ acc[ri][0]=0; acc[ri][1]=0; acc[ri][2]=0; acc[ri][3]=0; }
    for(int k = 0; k < HD; k += 2){
        float4 wa = *(const float4*)&sW[k*64 + tc*4];
        float4 wb = *(const float4*)&sW[(k+1)*64 + tc*4];
        #pragma unroll
        for(int ri = 0; ri < 8; ri++){
            float2 a = *(const float2*)&sHt[(tr*8 + ri)*66 + k];
            acc[ri][0] += a.x*wa.x; acc[ri][1] += a.x*wa.y;
            acc[ri][2] += a.x*wa.z; acc[ri][3] += a.x*wa.w;
            acc[ri][0] += a.y*wb.x; acc[ri][1] += a.y*wb.y;
            acc[ri][2] += a.y*wb.z; acc[ri][3] += a.y*wb.w;
        }
    }
    float* xo = g_x[gph];
    #pragma unroll
    for(int ri = 0; ri < 8; ri++){
        int row = r0 + tr*8 + ri;
        float4 o; o.x = acc[ri][0]; o.y = acc[ri][1]; o.z = acc[ri][2]; o.w = acc[ri][3];
        *(float4*)&xo[row*HD + tc*4] = o;
    }
}

// ---------------- CSR aggregation: int2 index stream + 2-edge unroll ----------------
__global__ void k_agg(int l){
    const int gph = blockIdx.y;
    const int t = threadIdx.x;
    const int f2 = t & 31;
    const int dq = t >> 5;
    const int dst = blockIdx.x*8 + dq;
    const int eofs = (gph == 0) ? 0 : ((gph == 1) ? E1N : (E1N + E2N));
    const int s = g_rs[gph*(ATN+1) + dst];
    const int e = g_rs[gph*(ATN+1) + dst + 1];
    const u64* __restrict__ xq = (const u64*)g_x[gph];
    const u64* __restrict__ Wq = (const u64*)(g_W + (size_t)l*ETN*HD) + (size_t)eofs*32;
    u64 acc[NB];
    #pragma unroll
    for(int b = 0; b < NB; b++) acc[b] = 0ull;
    int p = s;
    for(; p + 1 < e; p += 2){
        int2 c0 = __ldg(&g_csr[eofs + p]);
        int2 c1 = __ldg(&g_csr[eofs + p + 1]);
        u64 w0 = Wq[(size_t)c0.y*32 + f2];
        u64 w1 = Wq[(size_t)c1.y*32 + f2];
        int base0 = c0.x*32 + f2;
        int base1 = c1.x*32 + f2;
        #pragma unroll
        for(int b = 0; b < NB; b++){
            fma2(acc[b], xq[base0 + b*ATN*32], w0);
            fma2(acc[b], xq[base1 + b*ATN*32], w1);
        }
    }
    if(p < e){
        int2 c0 = __ldg(&g_csr[eofs + p]);
        u64 w0 = Wq[(size_t)c0.y*32 + f2];
        int base0 = c0.x*32 + f2;
        #pragma unroll
        for(int b = 0; b < NB; b++)
            fma2(acc[b], xq[base0 + b*ATN*32], w0);
    }
    u64* aq = (u64*)g_agg[gph];
    int ob = dst*32 + f2;
    #pragma unroll
    for(int b = 0; b < NB; b++)
        aq[ob + b*ATN*32] = acc[b];
}

// ---------------- block (32-row) + fused next-layer lin1 ----------------
__global__ void k_block(const float* __restrict__ cw2, const float* __restrict__ cb2,
                        const float* __restrict__ bw, const float* __restrict__ bb,
                        const float* __restrict__ cw1, int l, int next){
    const int r0 = blockIdx.x * 32;
    const int t = threadIdx.x, tc = t & 15, tr = t >> 4;
    __shared__ __align__(16) float sW[64*64];
    __shared__ __align__(16) float sAg[32*66];
    __shared__ __align__(16) float sT[32*66];
    float hacc[4][4];
    #pragma unroll
    for(int ri = 0; ri < 4; ri++){ hacc[ri][0]=0; hacc[ri][1]=0; hacc[ri][2]=0; hacc[ri][3]=0; }

    for(int g = 0; g < 3; g++){
        const float* w = cw2 + (l*3 + g)*HD*HD;
        for(int i = t; i < HD*HD; i += 128) sW[i] = w[i];
        const float* ag = g_agg[g];
        for(int i = t; i < 32*64; i += 128){
            int rr = i >> 6, kk = i & 63;
            sAg[rr*66 + kk] = ag[(r0 + rr)*HD + kk];
        }
        __syncthreads();

        float acc[4][4];
        #pragma unroll
        for(int ri = 0; ri < 4; ri++){ acc[ri][0]=0; acc[ri][1]=0; acc[ri][2]=0; acc[ri][3]=0; }
        for(int k = 0; k < HD; k += 2){
            float4 wa = *(const float4*)&sW[k*64 + tc*4];
            float4 wb = *(const float4*)&sW[(k+1)*64 + tc*4];
            #pragma unroll
            for(int ri = 0; ri < 4; ri++){
                float2 a = *(const float2*)&sAg[(tr*4 + ri)*66 + k];
                acc[ri][0] += a.x*wa.x; acc[ri][1] += a.x*wa.y;
                acc[ri][2] += a.x*wa.z; acc[ri][3] += a.x*wa.w;
                acc[ri][0] += a.y*wb.x; acc[ri][1] += a.y*wb.y;
                acc[ri][2] += a.y*wb.z; acc[ri][3] += a.y*wb.w;
            }
        }
        float b2v[4];
        #pragma unroll
        for(int j = 0; j < 4; j++) b2v[j] = cb2[(l*3 + g)*HD + tc*4 + j];
        #pragma unroll
        for(int ri = 0; ri < 4; ri++)
            #pragma unroll
            for(int j = 0; j < 4; j++)
                sT[(tr*4 + ri)*66 + tc*4 + j] = sspf(acc[ri][j] + b2v[j]);
        __syncthreads();

        const float* w2 = bw + (l*3 + g)*HD*HD;
        for(int i = t; i < HD*HD; i += 128) sW[i] = w2[i];
        __syncthreads();

        for(int k = 0; k < HD; k += 2){
            float4 wa = *(const float4*)&sW[k*64 + tc*4];
            float4 wb = *(const float4*)&sW[(k+1)*64 + tc*4];
            #pragma unroll
            for(int ri = 0; ri < 4; ri++){
                float2 a = *(const float2*)&sT[(tr*4 + ri)*66 + k];
                hacc[ri][0] += a.x*wa.x; hacc[ri][1] += a.x*wa.y;
                hacc[ri][2] += a.x*wa.z; hacc[ri][3] += a.x*wa.w;
                hacc[ri][0] += a.y*wb.x; hacc[ri][1] += a.y*wb.y;
                hacc[ri][2] += a.y*wb.z; hacc[ri][3] += a.y*wb.w;
            }
        }
        float bbv[4];
        #pragma unroll
        for(int j = 0; j < 4; j++) bbv[j] = bb[(l*3 + g)*HD + tc*4 + j];
        #pragma unroll
        for(int ri = 0; ri < 4; ri++)
            #pragma unroll
            for(int j = 0; j < 4; j++) hacc[ri][j] += bbv[j];
        __syncthreads();
    }

    // h += delta; stash updated h rows in sAg for the fused lin1
    #pragma unroll
    for(int ri = 0; ri < 4; ri++){
        int row = r0 + tr*4 + ri;
        float4* hp = (float4*)&g_h[row*HD + tc*4];
        float4 hv = *hp;
        hv.x += hacc[ri][0]; hv.y += hacc[ri][1];
        hv.z += hacc[ri][2]; hv.w += hacc[ri][3];
        *hp = hv;
        float* sr = &sAg[(tr*4 + ri)*66 + tc*4];
        sr[0] = hv.x; sr[1] = hv.y; sr[2] = hv.z; sr[3] = hv.w;
    }

    if(next){
        for(int g = 0; g < 3; g++){
            const float* w = cw1 + ((l+1)*3 + g)*HD*HD;
            for(int i = t; i < HD*HD; i += 128) sW[i] = w[i];
            __syncthreads();   // covers sAg stores on first iteration
            float acc[4][4];
            #pragma unroll
            for(int ri = 0; ri < 4; ri++){ acc[ri][0]=0; acc[ri][1]=0; acc[ri][2]=0; acc[ri][3]=0; }
            for(int k = 0; k < HD; k += 2){
                float4 wa = *(const float4*)&sW[k*64 + tc*4];
                float4 wb = *(const float4*)&sW[(k+1)*64 + tc*4];
                #pragma unroll
                for(int ri = 0; ri < 4; ri++){
                    float2 a = *(const float2*)&sAg[(tr*4 + ri)*66 + k];
                    acc[ri][0] += a.x*wa.x; acc[ri][1] += a.x*wa.y;
                    acc[ri][2] += a.x*wa.z; acc[ri][3] += a.x*wa.w;
                    acc[ri][0] += a.y*wb.x; acc[ri][1] += a.y*wb.y;
                    acc[ri][2] += a.y*wb.z; acc[ri][3] += a.y*wb.w;
                }
            }
            float* xo = g_x[g];
            #pragma unroll
            for(int ri = 0; ri < 4; ri++){
                int row = r0 + tr*4 + ri;
                float4 o; o.x = acc[ri][0]; o.y = acc[ri][1]; o.z = acc[ri][2]; o.w = acc[ri][3];
                *(float4*)&xo[row*HD + tc*4] = o;
            }
            __syncthreads();   // before next g overwrites sW
        }
    }
}

__global__ void k_readout(const float* __restrict__ ow1, const float* __restrict__ ob1,
                          const float* __restrict__ ow2, const float* __restrict__ ob2,
                          float* __restrict__ out){
    __shared__ float sS[NB*HD];
    __shared__ float sV[NB*32];
    int t = threadIdx.x;
    int b = t >> 6, f = t & 63;
    float s = 0.0f;
    const float* hp = g_h + (size_t)(b*ATN + M1N)*HD + f;
    #pragma unroll 4
    for(int i = 0; i < M2N; i++) s += hp[(size_t)i*HD];
    sS[b*HD + f] = s;
    __syncthreads();
    if(t < NB*32){
        int b2 = t >> 5, j = t & 31;
        float v = 0.0f;
        #pragma unroll 8
        for(int f2 = 0; f2 < HD; f2++) v += sS[b2*HD + f2] * ow1[f2*32 + j];
        sV[b2*32 + j] = v + (float)M2N * ob1[j];
    }
    __syncthreads();
    if(t < NB){
        float o = 0.0f;
        #pragma unroll
        for(int j = 0; j < 32; j++) o += sV[t*32 + j] * ow2[j];
        out[t] = o + (float)M2N * ob2[0];
    }
}

extern "C" void kernel_launch(void* const* d_in, const int* in_sizes, int n_in,
                              void* d_out, int out_size){
    (void)in_sizes; (void)n_in; (void)out_size;
    const int*   sites  = (const int*)d_in[0];
    const int*   sitesp = (const int*)d_in[1];
    const int*   ei1 = (const int*)d_in[2];
    const float* ew1 = (const float*)d_in[3];
    const int*   c1  = (const int*)d_in[4];
    const int*   ei2 = (const int*)d_in[5];
    const float* ew2 = (const float*)d_in[6];
    const int*   c2  = (const int*)d_in[7];
    const int*   ei3 = (const int*)d_in[8];
    const float* ew3 = (const float*)d_in[9];
    const int*   c3  = (const int*)d_in[10];
    const float* embw  = (const float*)d_in[11];
    const float* embpw = (const float*)d_in[12];
    const float* mw1 = (const float*)d_in[13];
    const float* mb1 = (const float*)d_in[14];
    const float* mw2 = (const float*)d_in[15];
    const float* mb2 = (const float*)d_in[16];
    const float* cw1 = (const float*)d_in[17];
    const float* cw2 = (const float*)d_in[18];
    const float* cb2 = (const float*)d_in[19];
    const float* bw  = (const float*)d_in[20];
    const float* bb  = (const float*)d_in[21];
    const float* ow1 = (const float*)d_in[22];
    const float* ob1 = (const float*)d_in[23];
    const float* ow2 = (const float*)d_in[24];
    const float* ob2 = (const float*)d_in[25];
    float* out = (float*)d_out;

    k_count<<<(ETN + 255)/256, 256>>>(ei1, ei2, ei3, ew1, ew2, ew3, c1, c2, c3); // 1
    k_cbase_rs<<<3, 32>>>();                                                     // 2
    k_fill<<<(ETN + 255)/256, 256>>>(ei1, ei2, ei3, ew1, ew2, ew3, c1, c2, c3);  // 3

    dim3 gw((E1N + 63)/64, CN, LN*3);
    k_wmlp<<<gw, 128>>>(mw1, mb1, mw2, mb2);                                     // 4 <- profiled
    k_embed<<<(NN*HD + 255)/256, 256>>>(sites, sitesp, embw, embpw);
    k_lin1<<<dim3(NN/64, 3), 128>>>(cw1, 0);

    for(int l = 0; l < LN; l++){
        k_agg<<<dim3(ATN/8, 3), 256>>>(l);
        k_block<<<NN/32, 128>>>(cw2, cb2, bw, bb, cw1, l, (l + 1 < LN) ? 1 : 0);
    }
    k_readout<<<1, 512>>>(ow1, ob1, ow2, ob2, out);
    k_cleanup<<<(3*ATN + 255)/256, 256>>>();
}

// round 17
// speedup vs baseline: 1.6103x; 1.1133x over previous
#include <cuda_runtime.h>
#include <math.h>

#define NB 8
#define M1N 2000
#define M2N 400
#define ATN 2400
#define NN (NB*ATN)
#define HD 64
#define NGN 50
#define NBUK 50
#define LN 4
#define CN 4
#define E1N 60000
#define E2N 20000
#define E3N 20000
#define ETN 100000
#define RCH 5            // readout chunks per batch (400/5 = 80 rows)

typedef unsigned long long u64;

__device__ float g_h[NN*HD];
__device__ float g_x[3][NN*HD];
__device__ float g_agg[3][NN*HD];
__device__ float g_W[LN*ETN*HD];
__device__ float g_d[ETN];
__device__ float g_ccut[ETN];
__device__ int   g_kq[ETN];
__device__ int2  g_csr[ETN];
__device__ int   g_cnt[3*ATN];        // zero-init; re-zeroed by k_cleanup
__device__ int   g_cur[3*ATN];
__device__ int   g_rs[3*(ATN+1)];
__device__ int   g_cc2[3*CN*NBUK];
__device__ int   g_ccur2[3*CN*NBUK];
__device__ int   g_cb2[3*CN*NBUK];
__device__ float g_rpart[NB*RCH*HD];

// fast shifted-softplus: max(x,0) + log(1+exp(-|x|)) - log2
__device__ __forceinline__ float sspf(float x){
    return fmaxf(x, 0.0f) + __logf(1.0f + __expf(-fabsf(x))) - 0.6931471805599453f;
}

__device__ __forceinline__ void fma2(u64& d, u64 a, u64 b){
    asm("fma.rn.f32x2 %0, %1, %2, %0;" : "+l"(d) : "l"(a), "l"(b));
}

__device__ __forceinline__ int bucket_of(float d){
    int b = (int)(d * 4.9f);
    return min(NBUK-1, max(0, b));
}

__device__ __forceinline__ void resolve_edge(int idx, int& g, int& e, int& eofs){
    if(idx < E1N){ g = 0; e = idx; eofs = 0; }
    else if(idx < E1N+E2N){ g = 1; e = idx-E1N; eofs = E1N; }
    else { g = 2; e = idx-E1N-E2N; eofs = E1N+E2N; }
}

// ---------------- preprocessing ----------------
__global__ void k_count(const int* __restrict__ e1, const int* __restrict__ e2,
                        const int* __restrict__ e3,
                        const float* __restrict__ w1, const float* __restrict__ w2,
                        const float* __restrict__ w3,
                        const int* __restrict__ c1, const int* __restrict__ c2,
                        const int* __restrict__ c3){
    int idx = blockIdx.x*blockDim.x + threadIdx.x;
    if(idx >= ETN) return;
    int g, e, eofs; resolve_edge(idx, g, e, eofs);
    const int* cp  = (g==0) ? c1 : ((g==1) ? c2 : c3);
    const int* eip = (g==0) ? e1 : ((g==1) ? e2 : e3);
    const float* wp = (g==0) ? w1 : ((g==1) ? w2 : w3);
    int b = bucket_of(wp[e]);
    atomicAdd(&g_cc2[(g*CN + cp[e])*NBUK + b], 1);
    atomicAdd(&g_cnt[g*ATN + eip[2*e + 1]], 1);
}

__global__ void k_cbase_rs(){
    int g = blockIdx.x;
    int lane = threadIdx.x;
    {
        const int per = ATN / 32;
        int base = lane * per;
        int sum = 0;
        for(int i = 0; i < per; i++) sum += g_cnt[g*ATN + base + i];
        int incl = sum;
        #pragma unroll
        for(int o = 1; o < 32; o <<= 1){
            int v = __shfl_up_sync(0xFFFFFFFFu, incl, o);
            if(lane >= o) incl += v;
        }
        int run = incl - sum;
        for(int i = 0; i < per; i++){
            g_rs[g*(ATN+1) + base + i] = run;
            run += g_cnt[g*ATN + base + i];
        }
        if(lane == 31) g_rs[g*(ATN+1) + ATN] = run;
    }
    {
        const int M = CN*NBUK;
        const int per = (M + 31) / 32;
        int base = lane * per;
        int sum = 0;
        for(int i = 0; i < per; i++){
            int id = base + i;
            if(id < M) sum += g_cc2[g*M + id];
        }
        int incl = sum;
        #pragma unroll
        for(int o = 1; o < 32; o <<= 1){
            int v = __shfl_up_sync(0xFFFFFFFFu, incl, o);
            if(lane >= o) incl += v;
        }
        int run = incl - sum;
        for(int i = 0; i < per; i++){
            int id = base + i;
            if(id < M){ g_cb2[g*M + id] = run; run += g_cc2[g*M + id]; }
        }
    }
}

__global__ void k_fill(const int* __restrict__ e1, const int* __restrict__ e2,
                       const int* __restrict__ e3,
                       const float* __restrict__ w1, const float* __restrict__ w2,
                       const float* __restrict__ w3,
                       const int* __restrict__ c1, const int* __restrict__ c2,
                       const int* __restrict__ c3){
    int idx = blockIdx.x*blockDim.x + threadIdx.x;
    if(idx >= ETN) return;
    int g, e, eofs; resolve_edge(idx, g, e, eofs);
    const int* cp  = (g==0) ? c1 : ((g==1) ? c2 : c3);
    const int* eip = (g==0) ? e1 : ((g==1) ? e2 : e3);
    const float* wp = (g==0) ? w1 : ((g==1) ? w2 : w3);
    int col = cp[e];
    float d = wp[e];
    int b = bucket_of(d);
    int slot = (g*CN + col)*NBUK + b;
    int p = g_cb2[slot] + atomicAdd(&g_ccur2[slot], 1);
    g_kq[eofs + p] = b;
    g_d[eofs + p] = d;
    g_ccut[eofs + p] = 0.5f * (cosf(d * 3.14159265358979323846f / 10.0f) + 1.0f);
    int src = eip[2*e], dst = eip[2*e + 1];
    int pc = g_rs[g*(ATN+1) + dst] + atomicAdd(&g_cur[g*ATN + dst], 1);
    g_csr[eofs + pc] = make_int2(src, p);
}

__global__ void k_embed(const int* __restrict__ sites, const int* __restrict__ sitesp,
                        const float* __restrict__ embw, const float* __restrict__ embpw){
    int idx = blockIdx.x*blockDim.x + threadIdx.x;
    if(idx >= NN*HD) return;
    int n = idx >> 6, f = idx & 63;
    int b = n / ATN, i = n - b*ATN;
    float v;
    if(i < M1N) v = embw[sites[b*M1N + i]*HD + f];
    else        v = embpw[sitesp[b*M2N + (i - M1N)]*HD + f];
    g_h[idx] = v;
}

__global__ void k_cleanup(){
    int i = blockIdx.x*blockDim.x + threadIdx.x;
    if(i < 3*ATN){ g_cnt[i] = 0; g_cur[i] = 0; }
    if(i < 3*CN*NBUK){ g_cc2[i] = 0; g_ccur2[i] = 0; }
}

// ---------------- edge-filter MLP (R16 form, measured 122us) ----------------
__global__ void k_wmlp(const float* __restrict__ mw1, const float* __restrict__ mb1,
                       const float* __restrict__ mw2, const float* __restrict__ mb2){
    const int c = blockIdx.y;
    const int lz = blockIdx.z;
    const int l = lz / 3, g = lz - l*3;
    const int eofs = (g == 0) ? 0 : ((g == 1) ? E1N : (E1N + E2N));
    const int etot = (g == 0) ? E1N : ((g == 1) ? E2N : E3N);
    const int cb = g_cb2[(g*CN + c)*NBUK];
    const int ce = (c == CN-1) ? etot : g_cb2[(g*CN + c + 1)*NBUK];
    const int r0 = cb + blockIdx.x*64;
    if(r0 >= ce) return;
    const int t = threadIdx.x;
    const int tc = t & 15, tr = t >> 4;

    __shared__ __align__(16) float sW[32*64];
    __shared__ __align__(16) float sU[64*66];

    const int b0 = g_kq[eofs + r0];
    const int b1 = g_kq[eofs + min(r0 + 63, ce - 1)];
    const int k0 = max(0, b0 - 6);
    const int kend = min(NGN - 1, b1 + 7);

    const int pgc = (l*3 + g)*CN + c;
    const float* w1 = mw1 + pgc*NGN*HD;
    {
        const float step = 10.0f / 49.0f;
        const float coeff = -0.5f / (step*step);
        int rr = t & 63;
        int half = t >> 6;
        int row = r0 + rr;
        float d = (row < ce) ? __ldg(&g_d[eofs + row]) : 1e30f;
        int Wd = kend - k0 + 1;
        int hw = (Wd + 1) >> 1;
        int ks = k0 + half*hw;
        int ke = min(kend, ks + hw - 1);
        float* su = &sU[rr*66];
        for(int kk = ks; kk <= ke; kk++){
            float tt = d - step * (float)kk;
            float v = __expf(coeff * tt * tt);
            su[kk] = (row < ce) ? v : 0.0f;
        }
    }

    float acc[8][4];
    #pragma unroll
    for(int ri = 0; ri < 8; ri++){ acc[ri][0]=0; acc[ri][1]=0; acc[ri][2]=0; acc[ri][3]=0; }
    for(int kb = k0; kb <= kend; kb += 32){
        int kh = min(kend, kb + 31);
        int nrows = kh - kb + 1;
        for(int i = t; i < nrows*HD; i += 128) sW[i] = w1[kb*HD + i];
        __syncthreads();
        const float* wrow = &sW[tc*4];
        const float* arow = &sU[tr*8*66 + kb];
        int nk = kh - kb + 1;
        for(int k = 0; k < nk; k++){
            float4 w = *(const float4*)(wrow + k*64);
            #pragma unroll
            for(int ri = 0; ri < 8; ri++){
                float a = arow[ri*66 + k];
                acc[ri][0] += a*w.x; acc[ri][1] += a*w.y;
                acc[ri][2] += a*w.z; acc[ri][3] += a*w.w;
            }
        }
        __syncthreads();
    }

    float b1v[4];
    #pragma unroll
    for(int j = 0; j < 4; j++) b1v[j] = mb1[pgc*HD + tc*4 + j];
    #pragma unroll
    for(int ri = 0; ri < 8; ri++)
        #pragma unroll
        for(int j = 0; j < 4; j++)
            sU[(tr*8 + ri)*66 + tc*4 + j] = sspf(acc[ri][j] + b1v[j]);

    const float* w2 = mw2 + pgc*HD*HD;
    float acc2[8][4];
    #pragma unroll
    for(int ri = 0; ri < 8; ri++){ acc2[ri][0]=0; acc2[ri][1]=0; acc2[ri][2]=0; acc2[ri][3]=0; }
    for(int kb2 = 0; kb2 < HD; kb2 += 32){
        for(int i = t; i < 32*HD; i += 128) sW[i] = w2[kb2*HD + i];
        __syncthreads();
        #pragma unroll 4
        for(int kk = 0; kk < 32; kk += 2){
            float4 wa = *(const float4*)&sW[kk*64 + tc*4];
            float4 wb = *(const float4*)&sW[(kk+1)*64 + tc*4];
            #pragma unroll
            for(int ri = 0; ri < 8; ri++){
                float2 a = *(const float2*)&sU[(tr*8 + ri)*66 + kb2 + kk];
                acc2[ri][0] += a.x*wa.x; acc2[ri][1] += a.x*wa.y;
                acc2[ri][2] += a.x*wa.z; acc2[ri][3] += a.x*wa.w;
                acc2[ri][0] += a.y*wb.x; acc2[ri][1] += a.y*wb.y;
                acc2[ri][2] += a.y*wb.z; acc2[ri][3] += a.y*wb.w;
            }
        }
        __syncthreads();
    }
    float b2v[4];
    #pragma unroll
    for(int j = 0; j < 4; j++) b2v[j] = mb2[pgc*HD + tc*4 + j];
    #pragma unroll
    for(int ri = 0; ri < 8; ri++){
        int row = r0 + tr*8 + ri;
        if(row < ce){
            float cc = g_ccut[eofs + row];
            float4 o;
            o.x = (acc2[ri][0] + b2v[0]) * cc;
            o.y = (acc2[ri][1] + b2v[1]) * cc;
            o.z = (acc2[ri][2] + b2v[2]) * cc;
            o.w = (acc2[ri][3] + b2v[3]) * cc;
            *(float4*)&g_W[(size_t)(l*ETN + eofs + row)*HD + tc*4] = o;
        }
    }
}

// ---------------- lin1 (layer 0 only) ----------------
__global__ void k_lin1(const float* __restrict__ cw1, int l){
    const int gph = blockIdx.y;
    const int r0 = blockIdx.x * 64;
    const int t = threadIdx.x, tc = t & 15, tr = t >> 4;
    __shared__ __align__(16) float sW[64*64];
    __shared__ __align__(16) float sHt[64*66];
    const float* w = cw1 + (l*3 + gph)*HD*HD;
    for(int i = t; i < HD*HD; i += 128) sW[i] = w[i];
    for(int i = t; i < 64*64; i += 128){
        int rr = i >> 6, kk = i & 63;
        sHt[rr*66 + kk] = g_h[(r0 + rr)*HD + kk];
    }
    __syncthreads();
    float acc[8][4];
    #pragma unroll
    for(int ri = 0; ri < 8; ri++){ acc[ri][0]=0; acc[ri][1]=0; acc[ri][2]=0; acc[ri][3]=0; }
    for(int k = 0; k < HD; k += 2){
        float4 wa = *(const float4*)&sW[k*64 + tc*4];
        float4 wb = *(const float4*)&sW[(k+1)*64 + tc*4];
        #pragma unroll
        for(int ri = 0; ri < 8; ri++){
            float2 a = *(const float2*)&sHt[(tr*8 + ri)*66 + k];
            acc[ri][0] += a.x*wa.x; acc[ri][1] += a.x*wa.y;
            acc[ri][2] += a.x*wa.z; acc[ri][3] += a.x*wa.w;
            acc[ri][0] += a.y*wb.x; acc[ri][1] += a.y*wb.y;
            acc[ri][2] += a.y*wb.z; acc[ri][3] += a.y*wb.w;
        }
    }
    float* xo = g_x[gph];
    #pragma unroll
    for(int ri = 0; ri < 8; ri++){
        int row = r0 + tr*8 + ri;
        float4 o; o.x = acc[ri][0]; o.y = acc[ri][1]; o.z = acc[ri][2]; o.w = acc[ri][3];
        *(float4*)&xo[row*HD + tc*4] = o;
    }
}

// ---------------- CSR aggregation (R16 form) ----------------
__global__ void k_agg(int l){
    const int gph = blockIdx.y;
    const int t = threadIdx.x;
    const int f2 = t & 31;
    const int dq = t >> 5;
    const int dst = blockIdx.x*8 + dq;
    const int eofs = (gph == 0) ? 0 : ((gph == 1) ? E1N : (E1N + E2N));
    const int s = g_rs[gph*(ATN+1) + dst];
    const int e = g_rs[gph*(ATN+1) + dst + 1];
    const u64* __restrict__ xq = (const u64*)g_x[gph];
    const u64* __restrict__ Wq = (const u64*)(g_W + (size_t)l*ETN*HD) + (size_t)eofs*32;
    u64 acc[NB];
    #pragma unroll
    for(int b = 0; b < NB; b++) acc[b] = 0ull;
    int p = s;
    for(; p + 1 < e; p += 2){
        int2 c0 = __ldg(&g_csr[eofs + p]);
        int2 c1 = __ldg(&g_csr[eofs + p + 1]);
        u64 w0 = Wq[(size_t)c0.y*32 + f2];
        u64 w1 = Wq[(size_t)c1.y*32 + f2];
        int base0 = c0.x*32 + f2;
        int base1 = c1.x*32 + f2;
        #pragma unroll
        for(int b = 0; b < NB; b++){
            fma2(acc[b], xq[base0 + b*ATN*32], w0);
            fma2(acc[b], xq[base1 + b*ATN*32], w1);
        }
    }
    if(p < e){
        int2 c0 = __ldg(&g_csr[eofs + p]);
        u64 w0 = Wq[(size_t)c0.y*32 + f2];
        int base0 = c0.x*32 + f2;
        #pragma unroll
        for(int b = 0; b < NB; b++)
            fma2(acc[b], xq[base0 + b*ATN*32], w0);
    }
    u64* aq = (u64*)g_agg[gph];
    int ob = dst*32 + f2;
    #pragma unroll
    for(int b = 0; b < NB; b++)
        aq[ob + b*ATN*32] = acc[b];
}

// ---------------- block: 64 rows / 256 threads, weights in 32-row halves ----------------
// tc = t&15 (16 col-groups x4), tr = t>>4 (16 row-groups x4) -> 64 rows
__global__ void k_block(const float* __restrict__ cw2, const float* __restrict__ cb2,
                        const float* __restrict__ bw, const float* __restrict__ bb,
                        const float* __restrict__ cw1, int l, int next){
    const int r0 = blockIdx.x * 64;
    const int t = threadIdx.x, tc = t & 15, tr = t >> 4;
    __shared__ __align__(16) float sW[32*64];   // 8KB weight half
    __shared__ __align__(16) float sAg[64*66];
    __shared__ __align__(16) float sT[64*66];
    float hacc[4][4];
    #pragma unroll
    for(int ri = 0; ri < 4; ri++){ hacc[ri][0]=0; hacc[ri][1]=0; hacc[ri][2]=0; hacc[ri][3]=0; }

    for(int g = 0; g < 3; g++){
        const float* ag = g_agg[g];
        for(int i = t; i < 64*64; i += 256){
            int rr = i >> 6, kk = i & 63;
            sAg[rr*66 + kk] = ag[(r0 + rr)*HD + kk];
        }
        // GEMM1: acc = sAg @ cw2, weights streamed in 32-row halves
        const float* w = cw2 + (l*3 + g)*HD*HD;
        float acc[4][4];
        #pragma unroll
        for(int ri = 0; ri < 4; ri++){ acc[ri][0]=0; acc[ri][1]=0; acc[ri][2]=0; acc[ri][3]=0; }
        for(int kb = 0; kb < HD; kb += 32){
            for(int i = t; i < 32*HD; i += 256) sW[i] = w[kb*HD + i];
            __syncthreads();   // also covers sAg fill on first half
            #pragma unroll 4
            for(int kk = 0; kk < 32; kk += 2){
                float4 wa = *(const float4*)&sW[kk*64 + tc*4];
                float4 wb = *(const float4*)&sW[(kk+1)*64 + tc*4];
                #pragma unroll
                for(int ri = 0; ri < 4; ri++){
                    float2 a = *(const float2*)&sAg[(tr*4 + ri)*66 + kb + kk];
                    acc[ri][0] += a.x*wa.x; acc[ri][1] += a.x*wa.y;
                    acc[ri][2] += a.x*wa.z; acc[ri][3] += a.x*wa.w;
                    acc[ri][0] += a.y*wb.x; acc[ri][1] += a.y*wb.y;
                    acc[ri][2] += a.y*wb.z; acc[ri][3] += a.y*wb.w;
                }
            }
            __syncthreads();
        }
        float b2v[4];
        #pragma unroll
        for(int j = 0; j < 4; j++) b2v[j] = cb2[(l*3 + g)*HD + tc*4 + j];
        #pragma unroll
        for(int ri = 0; ri < 4; ri++)
            #pragma unroll
            for(int j = 0; j < 4; j++)
                sT[(tr*4 + ri)*66 + tc*4 + j] = sspf(acc[ri][j] + b2v[j]);
        // GEMM2: hacc += ssp(..) @ bw
        const float* w2 = bw + (l*3 + g)*HD*HD;
        for(int kb = 0; kb < HD; kb += 32){
            for(int i = t; i < 32*HD; i += 256) sW[i] = w2[kb*HD + i];
            __syncthreads();   // covers sT writes on first half
            #pragma unroll 4
            for(int kk = 0; kk < 32; kk += 2){
                float4 wa = *(const float4*)&sW[kk*64 + tc*4];
                float4 wb = *(const float4*)&sW[(kk+1)*64 + tc*4];
                #pragma unroll
                for(int ri = 0; ri < 4; ri++){
                    float2 a = *(const float2*)&sT[(tr*4 + ri)*66 + kb + kk];
                    hacc[ri][0] += a.x*wa.x; hacc[ri][1] += a.x*wa.y;
                    hacc[ri][2] += a.x*wa.z; hacc[ri][3] += a.x*wa.w;
                    hacc[ri][0] += a.y*wb.x; hacc[ri][1] += a.y*wb.y;
                    hacc[ri][2] += a.y*wb.z; hacc[ri][3] += a.y*wb.w;
                }
            }
            __syncthreads();
        }
        float bbv[4];
        #pragma unroll
        for(int j = 0; j < 4; j++) bbv[j] = bb[(l*3 + g)*HD + tc*4 + j];
        #pragma unroll
        for(int ri = 0; ri < 4; ri++)
            #pragma unroll
            for(int j = 0; j < 4; j++) hacc[ri][j] += bbv[j];
    }

    // h += delta; stash updated h rows in sAg for the fused lin1
    #pragma unroll
    for(int ri = 0; ri < 4; ri++){
        int row = r0 + tr*4 + ri;
        float4* hp = (float4*)&g_h[row*HD + tc*4];
        float4 hv = *hp;
        hv.x += hacc[ri][0]; hv.y += hacc[ri][1];
        hv.z += hacc[ri][2]; hv.w += hacc[ri][3];
        *hp = hv;
        float* sr = &sAg[(tr*4 + ri)*66 + tc*4];
        sr[0] = hv.x; sr[1] = hv.y; sr[2] = hv.z; sr[3] = hv.w;
    }

    if(next){
        for(int g = 0; g < 3; g++){
            const float* w = cw1 + ((l+1)*3 + g)*HD*HD;
            float acc[4][4];
            #pragma unroll
            for(int ri = 0; ri < 4; ri++){ acc[ri][0]=0; acc[ri][1]=0; acc[ri][2]=0; acc[ri][3]=0; }
            for(int kb = 0; kb < HD; kb += 32){
                for(int i = t; i < 32*HD; i += 256) sW[i] = w[kb*HD + i];
                __syncthreads();   // covers sAg stash stores on first pass
                #pragma unroll 4
                for(int kk = 0; kk < 32; kk += 2){
                    float4 wa = *(const float4*)&sW[kk*64 + tc*4];
                    float4 wb = *(const float4*)&sW[(kk+1)*64 + tc*4];
                    #pragma unroll
                    for(int ri = 0; ri < 4; ri++){
                        float2 a = *(const float2*)&sAg[(tr*4 + ri)*66 + kb + kk];
                        acc[ri][0] += a.x*wa.x; acc[ri][1] += a.x*wa.y;
                        acc[ri][2] += a.x*wa.z; acc[ri][3] += a.x*wa.w;
                        acc[ri][0] += a.y*wb.x; acc[ri][1] += a.y*wb.y;
                        acc[ri][2] += a.y*wb.z; acc[ri][3] += a.y*wb.w;
                    }
                }
                __syncthreads();
            }
            float* xo = g_x[g];
            #pragma unroll
            for(int ri = 0; ri < 4; ri++){
                int row = r0 + tr*4 + ri;
                float4 o; o.x = acc[ri][0]; o.y = acc[ri][1]; o.z = acc[ri][2]; o.w = acc[ri][3];
                *(float4*)&xo[row*HD + tc*4] = o;
            }
        }
    }
}

// ---------------- parallel readout ----------------
__global__ void k_rsum(){
    // grid (RCH, NB), 64 threads: each block sums M2N/RCH rows of one batch
    int chunk = blockIdx.x, b = blockIdx.y;
    int f = threadIdx.x;
    const int per = M2N / RCH;
    float s = 0.0f;
    const float* hp = g_h + (size_t)(b*ATN + M1N + chunk*per)*HD + f;
    #pragma unroll 4
    for(int i = 0; i < per; i++) s += hp[(size_t)i*HD];
    g_rpart[(b*RCH + chunk)*HD + f] = s;
}

__global__ void k_rout(const float* __restrict__ ow1, const float* __restrict__ ob1,
                       const float* __restrict__ ow2, const float* __restrict__ ob2,
                       float* __restrict__ out){
    __shared__ float sS[NB*HD];
    __shared__ float sV[NB*32];
    int t = threadIdx.x;
    if(t < NB*HD){
        int b = t >> 6, f = t & 63;
        float s = 0.0f;
        #pragma unroll
        for(int c = 0; c < RCH; c++) s += g_rpart[(b*RCH + c)*HD + f];
        sS[b*HD + f] = s;
    }
    __syncthreads();
    if(t < NB*32){
        int b2 = t >> 5, j = t & 31;
        float v = 0.0f;
        #pragma unroll 8
        for(int f2 = 0; f2 < HD; f2++) v += sS[b2*HD + f2] * ow1[f2*32 + j];
        sV[b2*32 + j] = v + (float)M2N * ob1[j];
    }
    __syncthreads();
    if(t < NB){
        float o = 0.0f;
        #pragma unroll
        for(int j = 0; j < 32; j++) o += sV[t*32 + j] * ow2[j];
        out[t] = o + (float)M2N * ob2[0];
    }
}

extern "C" void kernel_launch(void* const* d_in, const int* in_sizes, int n_in,
                              void* d_out, int out_size){
    (void)in_sizes; (void)n_in; (void)out_size;
    const int*   sites  = (const int*)d_in[0];
    const int*   sitesp = (const int*)d_in[1];
    const int*   ei1 = (const int*)d_in[2];
    const float* ew1 = (const float*)d_in[3];
    const int*   c1  = (const int*)d_in[4];
    const int*   ei2 = (const int*)d_in[5];
    const float* ew2 = (const float*)d_in[6];
    const int*   c2  = (const int*)d_in[7];
    const int*   ei3 = (const int*)d_in[8];
    const float* ew3 = (const float*)d_in[9];
    const int*   c3  = (const int*)d_in[10];
    const float* embw  = (const float*)d_in[11];
    const float* embpw = (const float*)d_in[12];
    const float* mw1 = (const float*)d_in[13];
    const float* mb1 = (const float*)d_in[14];
    const float* mw2 = (const float*)d_in[15];
    const float* mb2 = (const float*)d_in[16];
    const float* cw1 = (const float*)d_in[17];
    const float* cw2 = (const float*)d_in[18];
    const float* cb2 = (const float*)d_in[19];
    const float* bw  = (const float*)d_in[20];
    const float* bb  = (const float*)d_in[21];
    const float* ow1 = (const float*)d_in[22];
    const float* ob1 = (const float*)d_in[23];
    const float* ow2 = (const float*)d_in[24];
    const float* ob2 = (const float*)d_in[25];
    float* out = (float*)d_out;

    k_count<<<(ETN + 255)/256, 256>>>(ei1, ei2, ei3, ew1, ew2, ew3, c1, c2, c3); // 1
    k_cbase_rs<<<3, 32>>>();                                                     // 2
    k_fill<<<(ETN + 255)/256, 256>>>(ei1, ei2, ei3, ew1, ew2, ew3, c1, c2, c3);  // 3

    dim3 gw((E1N + 63)/64, CN, LN*3);
    k_wmlp<<<gw, 128>>>(mw1, mb1, mw2, mb2);                                     // 4 <- profiled
    k_embed<<<(NN*HD + 255)/256, 256>>>(sites, sitesp, embw, embpw);
    k_lin1<<<dim3(NN/64, 3), 128>>>(cw1, 0);

    for(int l = 0; l < LN; l++){
        k_agg<<<dim3(ATN/8, 3), 256>>>(l);
        k_block<<<NN/64, 256>>>(cw2, cb2, bw, bb, cw1, l, (l + 1 < LN) ? 1 : 0);
    }
    k_rsum<<<dim3(RCH, NB), 64>>>();
    k_rout<<<1, 512>>>(ow1, ob1, ow2, ob2, out);
    k_cleanup<<<(3*ATN + 255)/256, 256>>>();
}